// round 6
// baseline (speedup 1.0000x reference)
#include <cuda_runtime.h>
#include <cuda_bf16.h>
#include <cuda_fp16.h>
#include <math.h>
#include <stdint.h>

#define NN 100000
#define EE 1600000
#define HD 128
#define CD 40

// -------- scratch (static __device__ arrays; allocation forbidden) --------
__device__ __half g_hbuf[(size_t)NN * HD];  // 25.6 MB : GEMM out (gather src)
__device__ float  g_bufB[(size_t)NN * HD];  // 51.2 MB : agg out (GEMM in)
__device__ int    g_deg_out[NN];
__device__ int    g_deg_in[NN];
__device__ float  g_norm_out[NN];
__device__ float  g_norm_in[NN];
__device__ int    g_offs[NN + 1];
__device__ int    g_cursor[NN];
__device__ int    g_bsums[128];
__device__ int    g_csr[EE];                // 6.4 MB

// Pre-built W operand tiles: [n][k] bf16, padded row stride 136 elems, hi/lo.
__device__ __align__(16) unsigned char g_B0h[128 * 136 * 2];
__device__ __align__(16) unsigned char g_B0l[128 * 136 * 2];
__device__ __align__(16) unsigned char g_B1h[128 * 136 * 2];
__device__ __align__(16) unsigned char g_B1l[128 * 136 * 2];
__device__ __align__(16) unsigned char g_B2h[64 * 136 * 2];
__device__ __align__(16) unsigned char g_B2l[64 * 136 * 2];

// ===========================================================================
// MMA / ldmatrix helpers (baseline sm_80 features -- no 'a'-gated PTX)
// ===========================================================================
__device__ __forceinline__ uint32_t smem_to_u32(const void* p) {
    uint32_t a;
    asm("{ .reg .u64 t; cvta.to.shared.u64 t, %1; cvt.u32.u64 %0, t; }"
        : "=r"(a) : "l"(p));
    return a;
}

#define LDSM4(r, addr) \
    asm volatile("ldmatrix.sync.aligned.m8n8.x4.shared.b16 {%0,%1,%2,%3}, [%4];" \
        : "=r"((r)[0]), "=r"((r)[1]), "=r"((r)[2]), "=r"((r)[3]) : "r"(addr))

#define MMA_BF16(d, a, b0, b1) \
    asm volatile("mma.sync.aligned.m16n8k16.row.col.f32.bf16.bf16.f32 " \
        "{%0,%1,%2,%3}, {%4,%5,%6,%7}, {%8,%9}, {%0,%1,%2,%3};" \
        : "+f"((d)[0]), "+f"((d)[1]), "+f"((d)[2]), "+f"((d)[3]) \
        : "r"((a)[0]), "r"((a)[1]), "r"((a)[2]), "r"((a)[3]), "r"(b0), "r"(b1))

// ===========================================================================
// Degrees + norms + CSR build
// ===========================================================================
__global__ void k_zero() {
    int i = blockIdx.x * blockDim.x + threadIdx.x;
    if (i < NN) { g_deg_out[i] = 0; g_deg_in[i] = 0; g_cursor[i] = 0; }
}

__global__ void k_deg(const int* __restrict__ src, const int* __restrict__ dst) {
    int e = blockIdx.x * blockDim.x + threadIdx.x;
    if (e < EE) {
        atomicAdd(&g_deg_out[src[e]], 1);
        atomicAdd(&g_deg_in[dst[e]], 1);
    }
}

// Fused: per-node norms + W-tile build ([n][k] bf16 hi/lo, stride 136)
__global__ void k_norm_wtiles(const float* __restrict__ W0,
                              const float* __restrict__ W1,
                              const float* __restrict__ W2) {
    int i = blockIdx.x * blockDim.x + threadIdx.x;
    if (i < NN) {
        int d0 = g_deg_out[i];
        int d1 = g_deg_in[i];
        g_norm_out[i] = d0 > 0 ? rsqrtf((float)d0) : 0.f;
        g_norm_in[i]  = d1 > 0 ? rsqrtf((float)d1) : 0.f;
    }
    if (i < 40960) {
        float val;
        unsigned char *ph, *pl;
        int n, k;
        if (i < 32768) {
            const float* W = (i < 16384) ? W0 : W1;
            ph = (i < 16384) ? g_B0h : g_B1h;
            pl = (i < 16384) ? g_B0l : g_B1l;
            int e = i & 16383;
            n = e >> 7; k = e & 127;
            val = W[k * 128 + n];
        } else {
            int e = i - 32768;
            n = e >> 7; k = e & 127;      // n in [0,64)
            val = (n < CD) ? W2[k * CD + n] : 0.f;
            ph = g_B2h; pl = g_B2l;
        }
        __nv_bfloat16 hi = __float2bfloat16(val);
        __nv_bfloat16 lo = __float2bfloat16(val - __bfloat162float(hi));
        uint32_t off = ((uint32_t)n * 136u + (uint32_t)k) * 2u;
        *(__nv_bfloat16*)(ph + off) = hi;
        *(__nv_bfloat16*)(pl + off) = lo;
    }
}

__global__ void k_scan1() {
    __shared__ int sh[1024];
    int i = blockIdx.x * 1024 + threadIdx.x;
    int v = (i < NN) ? g_deg_in[i] : 0;
    sh[threadIdx.x] = v;
    __syncthreads();
    #pragma unroll
    for (int d = 1; d < 1024; d <<= 1) {
        int t = 0;
        if ((int)threadIdx.x >= d) t = sh[threadIdx.x - d];
        __syncthreads();
        sh[threadIdx.x] += t;
        __syncthreads();
    }
    if (i < NN) g_offs[i + 1] = sh[threadIdx.x];
    if (threadIdx.x == 1023) g_bsums[blockIdx.x] = sh[1023];
}

// Parallel exclusive scan of block sums (nb <= 128), one block.
__global__ void k_scan2(int nb) {
    __shared__ int sh[128];
    int t = threadIdx.x;
    int v = (t < nb) ? g_bsums[t] : 0;
    sh[t] = v;
    __syncthreads();
    #pragma unroll
    for (int d = 1; d < 128; d <<= 1) {
        int x = 0;
        if (t >= d) x = sh[t - d];
        __syncthreads();
        sh[t] += x;
        __syncthreads();
    }
    if (t < nb) g_bsums[t] = sh[t] - v;   // exclusive
}

__global__ void k_scan3() {
    int i = blockIdx.x * blockDim.x + threadIdx.x;
    if (i == 0) g_offs[0] = 0;
    if (i < NN) g_offs[i + 1] += g_bsums[i >> 10];
}

__global__ void k_scatter(const int* __restrict__ src, const int* __restrict__ dst) {
    int e = blockIdx.x * blockDim.x + threadIdx.x;
    if (e < EE) {
        int d = dst[e];
        int pos = g_offs[d] + atomicAdd(&g_cursor[d], 1);
        g_csr[pos] = src[e];
    }
}

// ===========================================================================
// HMMA GEMM: hout[r, 0:OUTC] = fp16( norm_out[r] * (x[r, 0:128] @ W) )
// CTA: MTILE rows x NTILE cols, 8 warps (4m x 2n). 3-term bf16 emulation.
// MTILE=64 -> smem ~102KB -> 2 CTAs/SM for cross-CTA latency hiding.
// ===========================================================================
template <int MTILE, int NTILE, int OUTC>
__global__ void __launch_bounds__(256)
gemm_mma(const float* __restrict__ xin,
         const unsigned char* __restrict__ Wh,
         const unsigned char* __restrict__ Wl,
         __half* __restrict__ hout) {
    extern __shared__ __align__(16) unsigned char sm[];
    constexpr int XS     = 136;
    constexpr int XH_OFF = 0;
    constexpr int XL_OFF = MTILE * XS * 2;
    constexpr int WH_OFF = XL_OFF * 2;
    constexpr int WBYTES = NTILE * XS * 2;
    constexpr int WL_OFF = WH_OFF + WBYTES;
    constexpr int NFRAG  = NTILE / 16;
    constexpr int NF2    = NFRAG / 2;
    constexpr int MI     = MTILE / 64;        // m16-frags per warp
    constexpr int KCHUNK = MTILE / 2;         // consecutive floats per thread

    const int tid  = threadIdx.x;
    const int wid  = tid >> 5;
    const int lane = tid & 31;
    const int row0 = blockIdx.x * MTILE;

    // ---- X: load fp32, split bf16 hi/lo, store to smem ----
    {
        int r  = tid & (MTILE - 1);
        int kh = (tid / MTILE) * KCHUNK;
        int gr = row0 + r;
        bool ok = gr < NN;
        const float4* xr = (const float4*)&xin[(size_t)gr * 128 + kh];
        uint32_t* xh32 = (uint32_t*)(sm + XH_OFF);
        uint32_t* xl32 = (uint32_t*)(sm + XL_OFF);
        int base32 = (r * XS + kh) >> 1;
        #pragma unroll
        for (int i = 0; i < MTILE / 16; i++) {     // 8 floats per iter
            float4 v0 = ok ? xr[i * 2]     : make_float4(0.f, 0.f, 0.f, 0.f);
            float4 v1 = ok ? xr[i * 2 + 1] : make_float4(0.f, 0.f, 0.f, 0.f);
            __nv_bfloat16 h0 = __float2bfloat16(v0.x), h1 = __float2bfloat16(v0.y);
            __nv_bfloat16 h2 = __float2bfloat16(v0.z), h3 = __float2bfloat16(v0.w);
            __nv_bfloat16 h4 = __float2bfloat16(v1.x), h5 = __float2bfloat16(v1.y);
            __nv_bfloat16 h6 = __float2bfloat16(v1.z), h7 = __float2bfloat16(v1.w);
            __nv_bfloat162 hp0(h0, h1), hp1(h2, h3), hp2(h4, h5), hp3(h6, h7);
            __nv_bfloat162 lp0(__float2bfloat16(v0.x - __bfloat162float(h0)),
                               __float2bfloat16(v0.y - __bfloat162float(h1)));
            __nv_bfloat162 lp1(__float2bfloat16(v0.z - __bfloat162float(h2)),
                               __float2bfloat16(v0.w - __bfloat162float(h3)));
            __nv_bfloat162 lp2(__float2bfloat16(v1.x - __bfloat162float(h4)),
                               __float2bfloat16(v1.y - __bfloat162float(h5)));
            __nv_bfloat162 lp3(__float2bfloat16(v1.z - __bfloat162float(h6)),
                               __float2bfloat16(v1.w - __bfloat162float(h7)));
            uint4 hv = make_uint4(*(uint32_t*)&hp0, *(uint32_t*)&hp1,
                                  *(uint32_t*)&hp2, *(uint32_t*)&hp3);
            uint4 lv = make_uint4(*(uint32_t*)&lp0, *(uint32_t*)&lp1,
                                  *(uint32_t*)&lp2, *(uint32_t*)&lp3);
            *(uint4*)&xh32[base32 + i * 4] = hv;
            *(uint4*)&xl32[base32 + i * 4] = lv;
        }
    }
    // ---- W: verbatim copy (prepped layout == smem layout) ----
    {
        const float4* s4h = (const float4*)Wh;
        const float4* s4l = (const float4*)Wl;
        float4* d4h = (float4*)(sm + WH_OFF);
        float4* d4l = (float4*)(sm + WL_OFF);
        #pragma unroll
        for (int i = tid; i < WBYTES / 16; i += 256) {
            d4h[i] = s4h[i];
            d4l[i] = s4l[i];
        }
    }
    __syncthreads();

    const int m0 = (wid & 3) * (MTILE / 4);
    const int n0 = (wid >> 2) * (NTILE / 2);
    const uint32_t smb = smem_to_u32(sm);
    uint32_t aH = smb + XH_OFF +
        (uint32_t)(((m0 + (lane & 15)) * XS + (lane >> 4) * 8) * 2);
    uint32_t aL = aH + (XL_OFF - XH_OFF);
    uint32_t bH = smb + WH_OFF +
        (uint32_t)(((n0 + (lane >> 4) * 8 + (lane & 7)) * XS + ((lane >> 3) & 1) * 8) * 2);
    uint32_t bL = bH + WBYTES;

    float acc[MI][NFRAG][4];
    #pragma unroll
    for (int mi = 0; mi < MI; mi++)
        #pragma unroll
        for (int f = 0; f < NFRAG; f++)
            #pragma unroll
            for (int q = 0; q < 4; q++) acc[mi][f][q] = 0.f;

    #pragma unroll
    for (int ks = 0; ks < 8; ks++) {
        uint32_t AH[MI][4], AL[MI][4];
        #pragma unroll
        for (int mi = 0; mi < MI; mi++) {
            LDSM4(AH[mi], aH + mi * 16 * XS * 2);
            LDSM4(AL[mi], aL + mi * 16 * XS * 2);
        }
        uint32_t BH[NF2][4], BL[NF2][4];
        #pragma unroll
        for (int j = 0; j < NF2; j++) {
            LDSM4(BH[j], bH + j * 16 * XS * 2);
            LDSM4(BL[j], bL + j * 16 * XS * 2);
        }
        #pragma unroll
        for (int mi = 0; mi < MI; mi++)
            #pragma unroll
            for (int j = 0; j < NF2; j++)
                #pragma unroll
                for (int h = 0; h < 2; h++) {
                    float* c = acc[mi][j * 2 + h];
                    MMA_BF16(c, AH[mi], BH[j][h * 2], BH[j][h * 2 + 1]);
                    MMA_BF16(c, AL[mi], BH[j][h * 2], BH[j][h * 2 + 1]);
                    MMA_BF16(c, AH[mi], BL[j][h * 2], BL[j][h * 2 + 1]);
                }
        aH += 32; aL += 32; bH += 32; bL += 32;
    }

    // ---- epilogue: scale by norm_out, store fp16 ----
    const int g  = lane >> 2;
    const int tq = lane & 3;
    #pragma unroll
    for (int mi = 0; mi < MI; mi++) {
        int r1 = row0 + m0 + mi * 16 + g;
        int r2 = r1 + 8;
        float s1 = (r1 < NN) ? g_norm_out[r1] : 0.f;
        float s2 = (r2 < NN) ? g_norm_out[r2] : 0.f;
        #pragma unroll
        for (int f = 0; f < NFRAG; f++) {
            int n = n0 + f * 8 + tq * 2;
            if (OUTC < NTILE && n >= OUTC) continue;
            float* c = acc[mi][f];
            if (r1 < NN) {
                __half2 hv = __floats2half2_rn(c[0] * s1, c[1] * s1);
                *(__half2*)&hout[(size_t)r1 * OUTC + n] = hv;
            }
            if (r2 < NN) {
                __half2 hv = __floats2half2_rn(c[2] * s2, c[3] * s2);
                *(__half2*)&hout[(size_t)r2 * OUTC + n] = hv;
            }
        }
    }
}

// ===========================================================================
// Aggregation 128-dim: one warp per dst node; CSR gather (fp16), fp32 accum.
// ===========================================================================
template <int RELU>
__global__ void __launch_bounds__(256)
agg128(const float* __restrict__ bias) {
    int w = (blockIdx.x * blockDim.x + threadIdx.x) >> 5;
    if (w >= NN) return;
    int lane = threadIdx.x & 31;
    int beg = g_offs[w], end = g_offs[w + 1];

    float4 acc = make_float4(0.f, 0.f, 0.f, 0.f);
    int e = beg;
    for (; e + 4 <= end; e += 4) {
        int s0 = g_csr[e],     s1 = g_csr[e + 1];
        int s2 = g_csr[e + 2], s3 = g_csr[e + 3];
        uint2 u0 = *(const uint2*)&g_hbuf[(size_t)s0 * 128 + lane * 4];
        uint2 u1 = *(const uint2*)&g_hbuf[(size_t)s1 * 128 + lane * 4];
        uint2 u2 = *(const uint2*)&g_hbuf[(size_t)s2 * 128 + lane * 4];
        uint2 u3 = *(const uint2*)&g_hbuf[(size_t)s3 * 128 + lane * 4];
        float2 a0 = __half22float2(*(__half2*)&u0.x), b0 = __half22float2(*(__half2*)&u0.y);
        float2 a1 = __half22float2(*(__half2*)&u1.x), b1 = __half22float2(*(__half2*)&u1.y);
        float2 a2 = __half22float2(*(__half2*)&u2.x), b2 = __half22float2(*(__half2*)&u2.y);
        float2 a3 = __half22float2(*(__half2*)&u3.x), b3 = __half22float2(*(__half2*)&u3.y);
        acc.x += (a0.x + a1.x) + (a2.x + a3.x);
        acc.y += (a0.y + a1.y) + (a2.y + a3.y);
        acc.z += (b0.x + b1.x) + (b2.x + b3.x);
        acc.w += (b0.y + b1.y) + (b2.y + b3.y);
    }
    for (; e < end; e++) {
        int s0 = g_csr[e];
        uint2 u0 = *(const uint2*)&g_hbuf[(size_t)s0 * 128 + lane * 4];
        float2 a0 = __half22float2(*(__half2*)&u0.x), b0 = __half22float2(*(__half2*)&u0.y);
        acc.x += a0.x; acc.y += a0.y; acc.z += b0.x; acc.w += b0.y;
    }

    float sc = g_norm_in[w];
    float4 b = *(const float4*)&bias[lane * 4];
    float4 o;
    o.x = fmaf(acc.x, sc, b.x);
    o.y = fmaf(acc.y, sc, b.y);
    o.z = fmaf(acc.z, sc, b.z);
    o.w = fmaf(acc.w, sc, b.w);
    if (RELU) {
        o.x = fmaxf(o.x, 0.f); o.y = fmaxf(o.y, 0.f);
        o.z = fmaxf(o.z, 0.f); o.w = fmaxf(o.w, 0.f);
    }
    *(float4*)&g_bufB[(size_t)w * 128 + lane * 4] = o;
}

// ===========================================================================
// Aggregation 40-dim (final layer, no relu) -> d_out (fp32)
// ===========================================================================
__global__ void __launch_bounds__(256)
agg40(const float* __restrict__ bias, float* __restrict__ out) {
    int w = (blockIdx.x * blockDim.x + threadIdx.x) >> 5;
    if (w >= NN) return;
    int lane = threadIdx.x & 31;
    int beg = g_offs[w], end = g_offs[w + 1];
    if (lane >= 20) return;

    float2 acc = make_float2(0.f, 0.f);
    int e = beg;
    for (; e + 2 <= end; e += 2) {
        int s0 = g_csr[e], s1 = g_csr[e + 1];
        __half2 h0 = *(const __half2*)&g_hbuf[(size_t)s0 * 40 + lane * 2];
        __half2 h1 = *(const __half2*)&g_hbuf[(size_t)s1 * 40 + lane * 2];
        float2 f0 = __half22float2(h0);
        float2 f1 = __half22float2(h1);
        acc.x += f0.x + f1.x;
        acc.y += f0.y + f1.y;
    }
    if (e < end) {
        int s0 = g_csr[e];
        float2 f0 = __half22float2(*(const __half2*)&g_hbuf[(size_t)s0 * 40 + lane * 2]);
        acc.x += f0.x; acc.y += f0.y;
    }
    float sc = g_norm_in[w];
    float2 o;
    o.x = fmaf(acc.x, sc, bias[lane * 2]);
    o.y = fmaf(acc.y, sc, bias[lane * 2 + 1]);
    *(float2*)&out[(size_t)w * 40 + lane * 2] = o;
}

// ===========================================================================
extern "C" void kernel_launch(void* const* d_in, const int* in_sizes, int n_in,
                              void* d_out, int out_size) {
    const float* feat = (const float*)d_in[0];
    const int*   src  = (const int*)  d_in[1];
    const int*   dst  = (const int*)  d_in[2];
    const float* W0   = (const float*)d_in[3];
    const float* b0   = (const float*)d_in[4];
    const float* W1   = (const float*)d_in[5];
    const float* b1   = (const float*)d_in[6];
    const float* W2   = (const float*)d_in[7];
    const float* b2   = (const float*)d_in[8];
    float* out = (float*)d_out;

    const int NB = (NN + 255) / 256;
    const int EB = (EE + 255) / 256;
    const int SB = (NN + 1023) / 1024;
    const int AGGB = (NN * 32 + 255) / 256;
    const int GB64 = (NN + 63) / 64;

    // smem: X(hi+lo) = 2*64*136*2 = 34816 ; W(hi+lo) = 2*NTILE*136*2
    const int SMEM_BIG   = 34816 + 2 * 128 * 136 * 2;  // 104448 -> 2 CTA/SM
    const int SMEM_SMALL = 34816 + 2 * 64 * 136 * 2;   // 69632  -> 3 CTA/SM
    static bool attr_done = false;
    if (!attr_done) {
        cudaFuncSetAttribute(gemm_mma<64, 128, 128>,
                             cudaFuncAttributeMaxDynamicSharedMemorySize, SMEM_BIG);
        cudaFuncSetAttribute(gemm_mma<64, 64, 40>,
                             cudaFuncAttributeMaxDynamicSharedMemorySize, SMEM_SMALL);
        attr_done = true;
    }

    unsigned char *p_B0h, *p_B0l, *p_B1h, *p_B1l, *p_B2h, *p_B2l;
    cudaGetSymbolAddress((void**)&p_B0h, g_B0h);
    cudaGetSymbolAddress((void**)&p_B0l, g_B0l);
    cudaGetSymbolAddress((void**)&p_B1h, g_B1h);
    cudaGetSymbolAddress((void**)&p_B1l, g_B1l);
    cudaGetSymbolAddress((void**)&p_B2h, g_B2h);
    cudaGetSymbolAddress((void**)&p_B2l, g_B2l);
    __half* p_hbuf;
    float*  p_bufB;
    cudaGetSymbolAddress((void**)&p_hbuf, g_hbuf);
    cudaGetSymbolAddress((void**)&p_bufB, g_bufB);

    // prep (ordered so gemm layer-0 is launch index 3 for ncu sampling)
    k_zero<<<NB, 256>>>();                               // 0
    k_deg<<<EB, 256>>>(src, dst);                        // 1
    k_norm_wtiles<<<NB, 256>>>(W0, W1, W2);              // 2
    gemm_mma<64, 128, 128><<<GB64, 256, SMEM_BIG>>>(     // 3  (layer 0 GEMM)
        feat, p_B0h, p_B0l, p_hbuf);
    k_scan1<<<SB, 1024>>>();                             // 4
    k_scan2<<<1, 128>>>(SB);                             // 5
    k_scan3<<<NB, 256>>>();                              // 6
    k_scatter<<<EB, 256>>>(src, dst);                    // 7

    // layer 0 aggregation
    agg128<1><<<AGGB, 256>>>(b0);                        // 8
    // layer 1
    gemm_mma<64, 128, 128><<<GB64, 256, SMEM_BIG>>>(p_bufB, p_B1h, p_B1l, p_hbuf);
    agg128<1><<<AGGB, 256>>>(b1);
    // layer 2
    gemm_mma<64, 64, 40><<<GB64, 256, SMEM_SMALL>>>(p_bufB, p_B2h, p_B2l, p_hbuf);
    agg40<<<AGGB, 256>>>(b2, out);
}

// round 7
// speedup vs baseline: 1.0123x; 1.0123x over previous
#include <cuda_runtime.h>
#include <cuda_bf16.h>
#include <cuda_fp16.h>
#include <math.h>
#include <stdint.h>

#define NN 100000
#define EE 1600000
#define HD 128
#define CD 40
#define NTILES 782            // ceil(NN/128)
#define PGRID 148             // persistent grid (1 CTA/SM)

// -------- scratch (static __device__ arrays; allocation forbidden) --------
__device__ __half g_hbuf[(size_t)NN * HD];  // 25.6 MB : GEMM out (gather src)
__device__ float  g_bufB[(size_t)NN * HD];  // 51.2 MB : agg out (GEMM in)
__device__ int    g_deg_out[NN];
__device__ int    g_deg_in[NN];
__device__ float  g_norm_out[NN];
__device__ float  g_norm_in[NN];
__device__ int    g_offs[NN + 1];
__device__ int    g_cursor[NN];
__device__ int    g_bsums[128];
__device__ int    g_csr[EE];                // 6.4 MB

// Pre-built W operand tiles: [n][k] bf16, padded row stride 136 elems, hi/lo.
__device__ __align__(16) unsigned char g_B0h[128 * 136 * 2];
__device__ __align__(16) unsigned char g_B0l[128 * 136 * 2];
__device__ __align__(16) unsigned char g_B1h[128 * 136 * 2];
__device__ __align__(16) unsigned char g_B1l[128 * 136 * 2];
__device__ __align__(16) unsigned char g_B2h[64 * 136 * 2];
__device__ __align__(16) unsigned char g_B2l[64 * 136 * 2];

// ===========================================================================
// helpers (baseline sm_80 features -- no 'a'-gated PTX)
// ===========================================================================
__device__ __forceinline__ uint32_t smem_to_u32(const void* p) {
    uint32_t a;
    asm("{ .reg .u64 t; cvta.to.shared.u64 t, %1; cvt.u32.u64 %0, t; }"
        : "=r"(a) : "l"(p));
    return a;
}

#define LDSM4(r, addr) \
    asm volatile("ldmatrix.sync.aligned.m8n8.x4.shared.b16 {%0,%1,%2,%3}, [%4];" \
        : "=r"((r)[0]), "=r"((r)[1]), "=r"((r)[2]), "=r"((r)[3]) : "r"(addr))

#define MMA_BF16(d, a, b0, b1) \
    asm volatile("mma.sync.aligned.m16n8k16.row.col.f32.bf16.bf16.f32 " \
        "{%0,%1,%2,%3}, {%4,%5,%6,%7}, {%8,%9}, {%0,%1,%2,%3};" \
        : "+f"((d)[0]), "+f"((d)[1]), "+f"((d)[2]), "+f"((d)[3]) \
        : "r"((a)[0]), "r"((a)[1]), "r"((a)[2]), "r"((a)[3]), "r"(b0), "r"(b1))

#define CP_ASYNC16(dst_u32, src_ptr) \
    asm volatile("cp.async.cg.shared.global [%0], [%1], 16;" \
        :: "r"(dst_u32), "l"(src_ptr) : "memory")
#define CP_COMMIT() asm volatile("cp.async.commit_group;" ::: "memory")
#define CP_WAIT0()  asm volatile("cp.async.wait_group 0;" ::: "memory")

// ===========================================================================
// Degrees + norms + CSR build
// ===========================================================================
__global__ void k_zero() {
    int i = blockIdx.x * blockDim.x + threadIdx.x;
    if (i < NN) { g_deg_out[i] = 0; g_deg_in[i] = 0; g_cursor[i] = 0; }
}

__global__ void k_deg(const int* __restrict__ src, const int* __restrict__ dst) {
    int e = blockIdx.x * blockDim.x + threadIdx.x;
    if (e < EE) {
        atomicAdd(&g_deg_out[src[e]], 1);
        atomicAdd(&g_deg_in[dst[e]], 1);
    }
}

// Fused: per-node norms + W-tile build ([n][k] bf16 hi/lo, stride 136)
__global__ void k_norm_wtiles(const float* __restrict__ W0,
                              const float* __restrict__ W1,
                              const float* __restrict__ W2) {
    int i = blockIdx.x * blockDim.x + threadIdx.x;
    if (i < NN) {
        int d0 = g_deg_out[i];
        int d1 = g_deg_in[i];
        g_norm_out[i] = d0 > 0 ? rsqrtf((float)d0) : 0.f;
        g_norm_in[i]  = d1 > 0 ? rsqrtf((float)d1) : 0.f;
    }
    if (i < 40960) {
        float val;
        unsigned char *ph, *pl;
        int n, k;
        if (i < 32768) {
            const float* W = (i < 16384) ? W0 : W1;
            ph = (i < 16384) ? g_B0h : g_B1h;
            pl = (i < 16384) ? g_B0l : g_B1l;
            int e = i & 16383;
            n = e >> 7; k = e & 127;
            val = W[k * 128 + n];
        } else {
            int e = i - 32768;
            n = e >> 7; k = e & 127;      // n in [0,64)
            val = (n < CD) ? W2[k * CD + n] : 0.f;
            ph = g_B2h; pl = g_B2l;
        }
        __nv_bfloat16 hi = __float2bfloat16(val);
        __nv_bfloat16 lo = __float2bfloat16(val - __bfloat162float(hi));
        uint32_t off = ((uint32_t)n * 136u + (uint32_t)k) * 2u;
        *(__nv_bfloat16*)(ph + off) = hi;
        *(__nv_bfloat16*)(pl + off) = lo;
    }
}

__global__ void k_scan1() {
    __shared__ int sh[1024];
    int i = blockIdx.x * 1024 + threadIdx.x;
    int v = (i < NN) ? g_deg_in[i] : 0;
    sh[threadIdx.x] = v;
    __syncthreads();
    #pragma unroll
    for (int d = 1; d < 1024; d <<= 1) {
        int t = 0;
        if ((int)threadIdx.x >= d) t = sh[threadIdx.x - d];
        __syncthreads();
        sh[threadIdx.x] += t;
        __syncthreads();
    }
    if (i < NN) g_offs[i + 1] = sh[threadIdx.x];
    if (threadIdx.x == 1023) g_bsums[blockIdx.x] = sh[1023];
}

// Parallel exclusive scan of block sums (nb <= 128), one block.
__global__ void k_scan2(int nb) {
    __shared__ int sh[128];
    int t = threadIdx.x;
    int v = (t < nb) ? g_bsums[t] : 0;
    sh[t] = v;
    __syncthreads();
    #pragma unroll
    for (int d = 1; d < 128; d <<= 1) {
        int x = 0;
        if (t >= d) x = sh[t - d];
        __syncthreads();
        sh[t] += x;
        __syncthreads();
    }
    if (t < nb) g_bsums[t] = sh[t] - v;   // exclusive
}

__global__ void k_scan3() {
    int i = blockIdx.x * blockDim.x + threadIdx.x;
    if (i == 0) g_offs[0] = 0;
    if (i < NN) g_offs[i + 1] += g_bsums[i >> 10];
}

__global__ void k_scatter(const int* __restrict__ src, const int* __restrict__ dst) {
    int e = blockIdx.x * blockDim.x + threadIdx.x;
    if (e < EE) {
        int d = dst[e];
        int pos = g_offs[d] + atomicAdd(&g_cursor[d], 1);
        g_csr[pos] = src[e];
    }
}

// ===========================================================================
// Persistent HMMA GEMM: hout[r,0:OUTC] = fp16(norm_out[r] * (x[r,:] @ W))
// grid=PGRID, 1 CTA/SM. W loaded to smem ONCE; X tiles (128 rows) stream in
// via cp.async double-pipe: prefetch tile t+1 during tile t's mainloop.
// 8 warps, warp tile 32m x (NTILE/2)n. 3-term bf16 emulation, fp32 accum.
// ===========================================================================
template <int NTILE, int OUTC>
__global__ void __launch_bounds__(256)
gemm_pers(const float* __restrict__ xin,
          const unsigned char* __restrict__ Wh,
          const unsigned char* __restrict__ Wl,
          __half* __restrict__ hout) {
    extern __shared__ __align__(16) unsigned char sm[];
    constexpr int XS      = 136;                   // bf16 row stride (elems)
    constexpr int SSTRIDE = 132;                   // stage row stride (floats)
    constexpr int XH_OFF  = 0;
    constexpr int XL_OFF  = 128 * XS * 2;          // 34816
    constexpr int WH_OFF  = XL_OFF * 2;            // 69632
    constexpr int WBYTES  = NTILE * XS * 2;
    constexpr int WL_OFF  = WH_OFF + WBYTES;
    constexpr int ST_OFF  = WL_OFF + WBYTES;
    constexpr int NFRAG   = NTILE / 16;
    constexpr int NF2     = NFRAG / 2;

    const int tid  = threadIdx.x;
    const int wid  = tid >> 5;
    const int lane = tid & 31;

    const uint32_t smb    = smem_to_u32(sm);
    const uint32_t st_smb = smb + ST_OFF;

    // prefetch lane mapping: 2 threads/row, 64 floats (16 x 16B) each
    const int pr = tid >> 1;
    const int ph = tid & 1;
    const uint32_t pdst = st_smb + (uint32_t)((pr * SSTRIDE + ph * 64) * 4);

    // ---- issue prefetch for first tile ----
    {
        int gr = blockIdx.x * 128 + pr;
        if (gr < NN) {
            const float* srcp = &xin[(size_t)gr * 128 + ph * 64];
            #pragma unroll
            for (int i = 0; i < 16; i++) CP_ASYNC16(pdst + i * 16, srcp + i * 4);
        } else {
            float4 z = make_float4(0.f, 0.f, 0.f, 0.f);
            #pragma unroll
            for (int i = 0; i < 16; i++)
                *(float4*)(sm + ST_OFF + (pr * SSTRIDE + ph * 64) * 4 + i * 16) = z;
        }
        CP_COMMIT();
    }

    // ---- W: copy once (overlaps with in-flight cp.async) ----
    {
        const float4* s4h = (const float4*)Wh;
        const float4* s4l = (const float4*)Wl;
        float4* d4h = (float4*)(sm + WH_OFF);
        float4* d4l = (float4*)(sm + WL_OFF);
        for (int i = tid; i < WBYTES / 16; i += 256) {
            d4h[i] = s4h[i];
            d4l[i] = s4l[i];
        }
    }

    // per-lane ldmatrix base offsets (constant across tiles)
    const int m0 = (wid & 3) * 32;
    const int n0 = (wid >> 2) * (NTILE / 2);
    const uint32_t aH0 = smb + XH_OFF +
        (uint32_t)(((m0 + (lane & 15)) * XS + (lane >> 4) * 8) * 2);
    const uint32_t bH0 = smb + WH_OFF +
        (uint32_t)(((n0 + (lane >> 4) * 8 + (lane & 7)) * XS + ((lane >> 3) & 1) * 8) * 2);

    // convert lane mapping: 1 row per thread half
    const int cr = tid & 127;
    const int ch = tid >> 7;               // 0/1 -> k-half
    const float4* stage4 = (const float4*)(sm + ST_OFF);
    const int sbase4 = cr * (SSTRIDE / 4) + ch * 16;
    uint32_t* xh32 = (uint32_t*)(sm + XH_OFF);
    uint32_t* xl32 = (uint32_t*)(sm + XL_OFF);
    const int cbase32 = (cr * XS + ch * 64) >> 1;

    const int g  = lane >> 2;
    const int tq = lane & 3;

    for (int t = blockIdx.x; t < NTILES; t += gridDim.x) {
        const int row0 = t * 128;

        CP_WAIT0();
        __syncthreads();           // stage ready; prev mainloop fully done

        // ---- convert stage (fp32) -> Xhi/Xlo (bf16) in smem ----
        #pragma unroll
        for (int i = 0; i < 8; i++) {
            float4 v0 = stage4[sbase4 + i * 2];
            float4 v1 = stage4[sbase4 + i * 2 + 1];
            __nv_bfloat16 h0 = __float2bfloat16(v0.x), h1 = __float2bfloat16(v0.y);
            __nv_bfloat16 h2 = __float2bfloat16(v0.z), h3 = __float2bfloat16(v0.w);
            __nv_bfloat16 h4 = __float2bfloat16(v1.x), h5 = __float2bfloat16(v1.y);
            __nv_bfloat16 h6 = __float2bfloat16(v1.z), h7 = __float2bfloat16(v1.w);
            __nv_bfloat162 hp0(h0, h1), hp1(h2, h3), hp2(h4, h5), hp3(h6, h7);
            __nv_bfloat162 lp0(__float2bfloat16(v0.x - __bfloat162float(h0)),
                               __float2bfloat16(v0.y - __bfloat162float(h1)));
            __nv_bfloat162 lp1(__float2bfloat16(v0.z - __bfloat162float(h2)),
                               __float2bfloat16(v0.w - __bfloat162float(h3)));
            __nv_bfloat162 lp2(__float2bfloat16(v1.x - __bfloat162float(h4)),
                               __float2bfloat16(v1.y - __bfloat162float(h5)));
            __nv_bfloat162 lp3(__float2bfloat16(v1.z - __bfloat162float(h6)),
                               __float2bfloat16(v1.w - __bfloat162float(h7)));
            uint4 hv = make_uint4(*(uint32_t*)&hp0, *(uint32_t*)&hp1,
                                  *(uint32_t*)&hp2, *(uint32_t*)&hp3);
            uint4 lv = make_uint4(*(uint32_t*)&lp0, *(uint32_t*)&lp1,
                                  *(uint32_t*)&lp2, *(uint32_t*)&lp3);
            *(uint4*)&xh32[cbase32 + i * 4] = hv;
            *(uint4*)&xl32[cbase32 + i * 4] = lv;
        }
        __syncthreads();           // Xhi/lo ready; stage free

        // ---- prefetch next tile (overlaps mainloop) ----
        {
            int tn = t + gridDim.x;
            if (tn < NTILES) {
                int gr = tn * 128 + pr;
                if (gr < NN) {
                    const float* srcp = &xin[(size_t)gr * 128 + ph * 64];
                    #pragma unroll
                    for (int i = 0; i < 16; i++) CP_ASYNC16(pdst + i * 16, srcp + i * 4);
                } else {
                    float4 z = make_float4(0.f, 0.f, 0.f, 0.f);
                    #pragma unroll
                    for (int i = 0; i < 16; i++)
                        *(float4*)(sm + ST_OFF + (pr * SSTRIDE + ph * 64) * 4 + i * 16) = z;
                }
            }
            CP_COMMIT();
        }

        // ---- mainloop: 8 k-steps of 16 ----
        float acc[2][NFRAG][4];
        #pragma unroll
        for (int mi = 0; mi < 2; mi++)
            #pragma unroll
            for (int f = 0; f < NFRAG; f++)
                #pragma unroll
                for (int q = 0; q < 4; q++) acc[mi][f][q] = 0.f;

        uint32_t aH = aH0, aL = aH0 + XL_OFF, bH = bH0, bL = bH0 + WBYTES;
        #pragma unroll
        for (int ks = 0; ks < 8; ks++) {
            uint32_t AH[2][4], AL[2][4];
            LDSM4(AH[0], aH);
            LDSM4(AH[1], aH + 16 * XS * 2);
            LDSM4(AL[0], aL);
            LDSM4(AL[1], aL + 16 * XS * 2);
            uint32_t BH[NF2][4], BL[NF2][4];
            #pragma unroll
            for (int j = 0; j < NF2; j++) {
                LDSM4(BH[j], bH + j * 16 * XS * 2);
                LDSM4(BL[j], bL + j * 16 * XS * 2);
            }
            #pragma unroll
            for (int mi = 0; mi < 2; mi++)
                #pragma unroll
                for (int j = 0; j < NF2; j++)
                    #pragma unroll
                    for (int h = 0; h < 2; h++) {
                        float* c = acc[mi][j * 2 + h];
                        MMA_BF16(c, AH[mi], BH[j][h * 2], BH[j][h * 2 + 1]);
                        MMA_BF16(c, AL[mi], BH[j][h * 2], BH[j][h * 2 + 1]);
                        MMA_BF16(c, AH[mi], BL[j][h * 2], BL[j][h * 2 + 1]);
                    }
            aH += 32; aL += 32; bH += 32; bL += 32;
        }

        // ---- epilogue: scale by norm_out, store fp16 ----
        #pragma unroll
        for (int mi = 0; mi < 2; mi++) {
            int r1 = row0 + m0 + mi * 16 + g;
            int r2 = r1 + 8;
            float s1 = (r1 < NN) ? g_norm_out[r1] : 0.f;
            float s2 = (r2 < NN) ? g_norm_out[r2] : 0.f;
            #pragma unroll
            for (int f = 0; f < NFRAG; f++) {
                int n = n0 + f * 8 + tq * 2;
                if (OUTC < NTILE && n >= OUTC) continue;
                float* c = acc[mi][f];
                if (r1 < NN) {
                    __half2 hv = __floats2half2_rn(c[0] * s1, c[1] * s1);
                    *(__half2*)&hout[(size_t)r1 * OUTC + n] = hv;
                }
                if (r2 < NN) {
                    __half2 hv = __floats2half2_rn(c[2] * s2, c[3] * s2);
                    *(__half2*)&hout[(size_t)r2 * OUTC + n] = hv;
                }
            }
        }
    }
}

// ===========================================================================
// Aggregation 128-dim: one warp per dst node; CSR gather (fp16), fp32 accum.
// ===========================================================================
template <int RELU>
__global__ void __launch_bounds__(256)
agg128(const float* __restrict__ bias) {
    int w = (blockIdx.x * blockDim.x + threadIdx.x) >> 5;
    if (w >= NN) return;
    int lane = threadIdx.x & 31;
    int beg = g_offs[w], end = g_offs[w + 1];

    float4 acc = make_float4(0.f, 0.f, 0.f, 0.f);
    int e = beg;
    for (; e + 4 <= end; e += 4) {
        int s0 = g_csr[e],     s1 = g_csr[e + 1];
        int s2 = g_csr[e + 2], s3 = g_csr[e + 3];
        uint2 u0 = *(const uint2*)&g_hbuf[(size_t)s0 * 128 + lane * 4];
        uint2 u1 = *(const uint2*)&g_hbuf[(size_t)s1 * 128 + lane * 4];
        uint2 u2 = *(const uint2*)&g_hbuf[(size_t)s2 * 128 + lane * 4];
        uint2 u3 = *(const uint2*)&g_hbuf[(size_t)s3 * 128 + lane * 4];
        float2 a0 = __half22float2(*(__half2*)&u0.x), b0 = __half22float2(*(__half2*)&u0.y);
        float2 a1 = __half22float2(*(__half2*)&u1.x), b1 = __half22float2(*(__half2*)&u1.y);
        float2 a2 = __half22float2(*(__half2*)&u2.x), b2 = __half22float2(*(__half2*)&u2.y);
        float2 a3 = __half22float2(*(__half2*)&u3.x), b3 = __half22float2(*(__half2*)&u3.y);
        acc.x += (a0.x + a1.x) + (a2.x + a3.x);
        acc.y += (a0.y + a1.y) + (a2.y + a3.y);
        acc.z += (b0.x + b1.x) + (b2.x + b3.x);
        acc.w += (b0.y + b1.y) + (b2.y + b3.y);
    }
    for (; e < end; e++) {
        int s0 = g_csr[e];
        uint2 u0 = *(const uint2*)&g_hbuf[(size_t)s0 * 128 + lane * 4];
        float2 a0 = __half22float2(*(__half2*)&u0.x), b0 = __half22float2(*(__half2*)&u0.y);
        acc.x += a0.x; acc.y += a0.y; acc.z += b0.x; acc.w += b0.y;
    }

    float sc = g_norm_in[w];
    float4 b = *(const float4*)&bias[lane * 4];
    float4 o;
    o.x = fmaf(acc.x, sc, b.x);
    o.y = fmaf(acc.y, sc, b.y);
    o.z = fmaf(acc.z, sc, b.z);
    o.w = fmaf(acc.w, sc, b.w);
    if (RELU) {
        o.x = fmaxf(o.x, 0.f); o.y = fmaxf(o.y, 0.f);
        o.z = fmaxf(o.z, 0.f); o.w = fmaxf(o.w, 0.f);
    }
    *(float4*)&g_bufB[(size_t)w * 128 + lane * 4] = o;
}

// ===========================================================================
// Aggregation 40-dim (final layer, no relu) -> d_out (fp32)
// ===========================================================================
__global__ void __launch_bounds__(256)
agg40(const float* __restrict__ bias, float* __restrict__ out) {
    int w = (blockIdx.x * blockDim.x + threadIdx.x) >> 5;
    if (w >= NN) return;
    int lane = threadIdx.x & 31;
    int beg = g_offs[w], end = g_offs[w + 1];
    if (lane >= 20) return;

    float2 acc = make_float2(0.f, 0.f);
    int e = beg;
    for (; e + 2 <= end; e += 2) {
        int s0 = g_csr[e], s1 = g_csr[e + 1];
        __half2 h0 = *(const __half2*)&g_hbuf[(size_t)s0 * 40 + lane * 2];
        __half2 h1 = *(const __half2*)&g_hbuf[(size_t)s1 * 40 + lane * 2];
        float2 f0 = __half22float2(h0);
        float2 f1 = __half22float2(h1);
        acc.x += f0.x + f1.x;
        acc.y += f0.y + f1.y;
    }
    if (e < end) {
        int s0 = g_csr[e];
        float2 f0 = __half22float2(*(const __half2*)&g_hbuf[(size_t)s0 * 40 + lane * 2]);
        acc.x += f0.x; acc.y += f0.y;
    }
    float sc = g_norm_in[w];
    float2 o;
    o.x = fmaf(acc.x, sc, bias[lane * 2]);
    o.y = fmaf(acc.y, sc, bias[lane * 2 + 1]);
    *(float2*)&out[(size_t)w * 40 + lane * 2] = o;
}

// ===========================================================================
extern "C" void kernel_launch(void* const* d_in, const int* in_sizes, int n_in,
                              void* d_out, int out_size) {
    const float* feat = (const float*)d_in[0];
    const int*   src  = (const int*)  d_in[1];
    const int*   dst  = (const int*)  d_in[2];
    const float* W0   = (const float*)d_in[3];
    const float* b0   = (const float*)d_in[4];
    const float* W1   = (const float*)d_in[5];
    const float* b1   = (const float*)d_in[6];
    const float* W2   = (const float*)d_in[7];
    const float* b2   = (const float*)d_in[8];
    float* out = (float*)d_out;

    const int NB = (NN + 255) / 256;
    const int EB = (EE + 255) / 256;
    const int SB = (NN + 1023) / 1024;
    const int AGGB = (NN * 32 + 255) / 256;

    // smem: Xhi/lo 69632 + W(hi+lo) + stage 128*132*4=67584
    const int SMEM_BIG   = 69632 + 2 * 128 * 136 * 2 + 67584;  // 206848
    const int SMEM_SMALL = 69632 + 2 * 64 * 136 * 2 + 67584;   // 172032
    static bool attr_done = false;
    if (!attr_done) {
        cudaFuncSetAttribute(gemm_pers<128, 128>,
                             cudaFuncAttributeMaxDynamicSharedMemorySize, SMEM_BIG);
        cudaFuncSetAttribute(gemm_pers<64, 40>,
                             cudaFuncAttributeMaxDynamicSharedMemorySize, SMEM_SMALL);
        attr_done = true;
    }

    unsigned char *p_B0h, *p_B0l, *p_B1h, *p_B1l, *p_B2h, *p_B2l;
    cudaGetSymbolAddress((void**)&p_B0h, g_B0h);
    cudaGetSymbolAddress((void**)&p_B0l, g_B0l);
    cudaGetSymbolAddress((void**)&p_B1h, g_B1h);
    cudaGetSymbolAddress((void**)&p_B1l, g_B1l);
    cudaGetSymbolAddress((void**)&p_B2h, g_B2h);
    cudaGetSymbolAddress((void**)&p_B2l, g_B2l);
    __half* p_hbuf;
    float*  p_bufB;
    cudaGetSymbolAddress((void**)&p_hbuf, g_hbuf);
    cudaGetSymbolAddress((void**)&p_bufB, g_bufB);

    // prep (gemm layer-0 kept at launch index 3 for ncu sampling)
    k_zero<<<NB, 256>>>();                               // 0
    k_deg<<<EB, 256>>>(src, dst);                        // 1
    k_norm_wtiles<<<NB, 256>>>(W0, W1, W2);              // 2
    gemm_pers<128, 128><<<PGRID, 256, SMEM_BIG>>>(       // 3 (layer 0 GEMM)
        feat, p_B0h, p_B0l, p_hbuf);
    k_scan1<<<SB, 1024>>>();                             // 4
    k_scan2<<<1, 128>>>(SB);                             // 5
    k_scan3<<<NB, 256>>>();                              // 6
    k_scatter<<<EB, 256>>>(src, dst);                    // 7

    // layer 0 aggregation
    agg128<1><<<AGGB, 256>>>(b0);
    // layer 1
    gemm_pers<128, 128><<<PGRID, 256, SMEM_BIG>>>(p_bufB, p_B1h, p_B1l, p_hbuf);
    agg128<1><<<AGGB, 256>>>(b1);
    // layer 2
    gemm_pers<64, 40><<<PGRID, 256, SMEM_SMALL>>>(p_bufB, p_B2h, p_B2l, p_hbuf);
    agg40<<<AGGB, 256>>>(b2, out);
}

// round 8
// speedup vs baseline: 1.0331x; 1.0205x over previous
#include <cuda_runtime.h>
#include <cuda_bf16.h>
#include <cuda_fp16.h>
#include <math.h>
#include <stdint.h>

#define NN 100000
#define EE 1600000
#define HD 128
#define CD 40
#define NTILES 782            // ceil(NN/128)
#define PGRID 148             // persistent grid (1 CTA/SM)

// -------- scratch (static __device__ arrays; allocation forbidden) --------
__device__ __half g_hbuf[(size_t)NN * HD];  // 25.6 MB : GEMM out (gather src)
__device__ float  g_bufB[(size_t)NN * HD];  // 51.2 MB : agg out (GEMM in)
__device__ int    g_deg_out[NN];
__device__ int    g_deg_in[NN];
__device__ float  g_norm_out[NN];
__device__ float  g_norm_in[NN];
__device__ int    g_offs[NN + 1];
__device__ int    g_cursor[NN];
__device__ int    g_bsums[128];
__device__ int    g_csr[EE];                // 6.4 MB

// Pre-built W operand tiles: [n][k] bf16, padded row stride 136 elems, hi/lo.
__device__ __align__(16) unsigned char g_B0h[128 * 136 * 2];
__device__ __align__(16) unsigned char g_B0l[128 * 136 * 2];
__device__ __align__(16) unsigned char g_B1h[128 * 136 * 2];
__device__ __align__(16) unsigned char g_B1l[128 * 136 * 2];
__device__ __align__(16) unsigned char g_B2h[64 * 136 * 2];
__device__ __align__(16) unsigned char g_B2l[64 * 136 * 2];

// ===========================================================================
// helpers (baseline sm_80 features -- no 'a'-gated PTX)
// ===========================================================================
__device__ __forceinline__ uint32_t smem_to_u32(const void* p) {
    uint32_t a;
    asm("{ .reg .u64 t; cvta.to.shared.u64 t, %1; cvt.u32.u64 %0, t; }"
        : "=r"(a) : "l"(p));
    return a;
}

#define LDSM4(r, addr) \
    asm volatile("ldmatrix.sync.aligned.m8n8.x4.shared.b16 {%0,%1,%2,%3}, [%4];" \
        : "=r"((r)[0]), "=r"((r)[1]), "=r"((r)[2]), "=r"((r)[3]) : "r"(addr))

#define MMA_BF16(d, a, b0, b1) \
    asm volatile("mma.sync.aligned.m16n8k16.row.col.f32.bf16.bf16.f32 " \
        "{%0,%1,%2,%3}, {%4,%5,%6,%7}, {%8,%9}, {%0,%1,%2,%3};" \
        : "+f"((d)[0]), "+f"((d)[1]), "+f"((d)[2]), "+f"((d)[3]) \
        : "r"((a)[0]), "r"((a)[1]), "r"((a)[2]), "r"((a)[3]), "r"(b0), "r"(b1))

#define CP_ASYNC16(dst_u32, src_ptr) \
    asm volatile("cp.async.cg.shared.global [%0], [%1], 16;" \
        :: "r"(dst_u32), "l"(src_ptr) : "memory")
#define CP_COMMIT() asm volatile("cp.async.commit_group;" ::: "memory")
#define CP_WAIT0()  asm volatile("cp.async.wait_group 0;" ::: "memory")

// ===========================================================================
// Degrees + norms + CSR build
// ===========================================================================
__global__ void k_zero() {
    int i = blockIdx.x * blockDim.x + threadIdx.x;
    if (i < NN) { g_deg_out[i] = 0; g_deg_in[i] = 0; g_cursor[i] = 0; }
}

__global__ void k_deg(const int* __restrict__ src, const int* __restrict__ dst) {
    int e = blockIdx.x * blockDim.x + threadIdx.x;
    if (e < EE) {
        atomicAdd(&g_deg_out[src[e]], 1);
        atomicAdd(&g_deg_in[dst[e]], 1);
    }
}

// Fused: per-node norms + W-tile build ([n][k] bf16 hi/lo, stride 136)
__global__ void k_norm_wtiles(const float* __restrict__ W0,
                              const float* __restrict__ W1,
                              const float* __restrict__ W2) {
    int i = blockIdx.x * blockDim.x + threadIdx.x;
    if (i < NN) {
        int d0 = g_deg_out[i];
        int d1 = g_deg_in[i];
        g_norm_out[i] = d0 > 0 ? rsqrtf((float)d0) : 0.f;
        g_norm_in[i]  = d1 > 0 ? rsqrtf((float)d1) : 0.f;
    }
    if (i < 40960) {
        float val;
        unsigned char *ph, *pl;
        int n, k;
        if (i < 32768) {
            const float* W = (i < 16384) ? W0 : W1;
            ph = (i < 16384) ? g_B0h : g_B1h;
            pl = (i < 16384) ? g_B0l : g_B1l;
            int e = i & 16383;
            n = e >> 7; k = e & 127;
            val = W[k * 128 + n];
        } else {
            int e = i - 32768;
            n = e >> 7; k = e & 127;      // n in [0,64)
            val = (n < CD) ? W2[k * CD + n] : 0.f;
            ph = g_B2h; pl = g_B2l;
        }
        __nv_bfloat16 hi = __float2bfloat16(val);
        __nv_bfloat16 lo = __float2bfloat16(val - __bfloat162float(hi));
        uint32_t off = ((uint32_t)n * 136u + (uint32_t)k) * 2u;
        *(__nv_bfloat16*)(ph + off) = hi;
        *(__nv_bfloat16*)(pl + off) = lo;
    }
}

__global__ void k_scan1() {
    __shared__ int sh[1024];
    int i = blockIdx.x * 1024 + threadIdx.x;
    int v = (i < NN) ? g_deg_in[i] : 0;
    sh[threadIdx.x] = v;
    __syncthreads();
    #pragma unroll
    for (int d = 1; d < 1024; d <<= 1) {
        int t = 0;
        if ((int)threadIdx.x >= d) t = sh[threadIdx.x - d];
        __syncthreads();
        sh[threadIdx.x] += t;
        __syncthreads();
    }
    if (i < NN) g_offs[i + 1] = sh[threadIdx.x];
    if (threadIdx.x == 1023) g_bsums[blockIdx.x] = sh[1023];
}

// Parallel exclusive scan of block sums (nb <= 128), one block.
__global__ void k_scan2(int nb) {
    __shared__ int sh[128];
    int t = threadIdx.x;
    int v = (t < nb) ? g_bsums[t] : 0;
    sh[t] = v;
    __syncthreads();
    #pragma unroll
    for (int d = 1; d < 128; d <<= 1) {
        int x = 0;
        if (t >= d) x = sh[t - d];
        __syncthreads();
        sh[t] += x;
        __syncthreads();
    }
    if (t < nb) g_bsums[t] = sh[t] - v;   // exclusive
}

__global__ void k_scan3() {
    int i = blockIdx.x * blockDim.x + threadIdx.x;
    if (i == 0) g_offs[0] = 0;
    if (i < NN) g_offs[i + 1] += g_bsums[i >> 10];
}

__global__ void k_scatter(const int* __restrict__ src, const int* __restrict__ dst) {
    int e = blockIdx.x * blockDim.x + threadIdx.x;
    if (e < EE) {
        int d = dst[e];
        int pos = g_offs[d] + atomicAdd(&g_cursor[d], 1);
        g_csr[pos] = src[e];
    }
}

// ===========================================================================
// Persistent HMMA GEMM: hout[r,0:OUTC] = fp16(norm_out[r] * (x[r,:] @ W))
// grid=PGRID, 512 threads (16 warps, 4/SMSP). W resident in smem; X tiles
// stream via cp.async. Warp tile 32m x (NTILE/4)n. 3-term bf16 emulation,
// TERM-MAJOR MMA order (independent accumulators between dependent MMAs).
// ===========================================================================
template <int NTILE, int OUTC>
__global__ void __launch_bounds__(512)
gemm_pers(const float* __restrict__ xin,
          const unsigned char* __restrict__ Wh,
          const unsigned char* __restrict__ Wl,
          __half* __restrict__ hout) {
    extern __shared__ __align__(16) unsigned char sm[];
    constexpr int XS      = 136;                   // bf16 row stride (elems)
    constexpr int SSTRIDE = 132;                   // stage row stride (floats)
    constexpr int XH_OFF  = 0;
    constexpr int XL_OFF  = 128 * XS * 2;          // 34816
    constexpr int WH_OFF  = XL_OFF * 2;            // 69632
    constexpr int WBYTES  = NTILE * XS * 2;
    constexpr int WL_OFF  = WH_OFF + WBYTES;
    constexpr int ST_OFF  = WL_OFF + WBYTES;
    constexpr int NWTILE  = NTILE / 4;             // warp n-tile (32 or 16)
    constexpr int NFRAG   = NWTILE / 8;            // n8 frags (4 or 2)
    constexpr int NF2     = NFRAG / 2;             // LDSM.x4 count (2 or 1)

    const int tid  = threadIdx.x;
    const int wid  = tid >> 5;
    const int lane = tid & 31;

    const uint32_t smb    = smem_to_u32(sm);
    const uint32_t st_smb = smb + ST_OFF;

    // prefetch lane mapping: 4 threads/row, 32 floats (8 x 16B) each
    const int pr = tid >> 2;
    const int ph = tid & 3;
    const uint32_t pdst = st_smb + (uint32_t)((pr * SSTRIDE + ph * 32) * 4);

    // ---- issue prefetch for first tile ----
    {
        int gr = blockIdx.x * 128 + pr;
        if (gr < NN) {
            const float* srcp = &xin[(size_t)gr * 128 + ph * 32];
            #pragma unroll
            for (int i = 0; i < 8; i++) CP_ASYNC16(pdst + i * 16, srcp + i * 4);
        } else {
            float4 z = make_float4(0.f, 0.f, 0.f, 0.f);
            #pragma unroll
            for (int i = 0; i < 8; i++)
                *(float4*)(sm + ST_OFF + (pr * SSTRIDE + ph * 32) * 4 + i * 16) = z;
        }
        CP_COMMIT();
    }

    // ---- W: copy once (overlaps with in-flight cp.async) ----
    {
        const float4* s4h = (const float4*)Wh;
        const float4* s4l = (const float4*)Wl;
        float4* d4h = (float4*)(sm + WH_OFF);
        float4* d4l = (float4*)(sm + WL_OFF);
        for (int i = tid; i < WBYTES / 16; i += 512) {
            d4h[i] = s4h[i];
            d4l[i] = s4l[i];
        }
    }

    // per-lane ldmatrix base offsets (constant across tiles)
    const int m0 = (wid & 3) * 32;
    const int n0 = (wid >> 2) * NWTILE;
    const uint32_t aH0 = smb + XH_OFF +
        (uint32_t)(((m0 + (lane & 15)) * XS + (lane >> 4) * 8) * 2);
    const uint32_t bH0 = smb + WH_OFF +
        (uint32_t)(((n0 + (lane >> 4) * 8 + (lane & 7)) * XS + ((lane >> 3) & 1) * 8) * 2);

    // convert lane mapping: 4 threads/row, 32 floats each (k-quarter)
    const int cr = tid & 127;
    const int ch = tid >> 7;               // 0..3 -> k-quarter
    const float4* stage4 = (const float4*)(sm + ST_OFF);
    const int sbase4 = cr * (SSTRIDE / 4) + ch * 8;
    uint32_t* xh32 = (uint32_t*)(sm + XH_OFF);
    uint32_t* xl32 = (uint32_t*)(sm + XL_OFF);
    const int cbase32 = (cr * XS + ch * 32) >> 1;

    const int g  = lane >> 2;
    const int tq = lane & 3;

    for (int t = blockIdx.x; t < NTILES; t += gridDim.x) {
        const int row0 = t * 128;

        CP_WAIT0();
        __syncthreads();           // stage ready; prev mainloop fully done

        // ---- convert stage (fp32) -> Xhi/Xlo (bf16) in smem ----
        #pragma unroll
        for (int i = 0; i < 4; i++) {
            float4 v0 = stage4[sbase4 + i * 2];
            float4 v1 = stage4[sbase4 + i * 2 + 1];
            __nv_bfloat16 h0 = __float2bfloat16(v0.x), h1 = __float2bfloat16(v0.y);
            __nv_bfloat16 h2 = __float2bfloat16(v0.z), h3 = __float2bfloat16(v0.w);
            __nv_bfloat16 h4 = __float2bfloat16(v1.x), h5 = __float2bfloat16(v1.y);
            __nv_bfloat16 h6 = __float2bfloat16(v1.z), h7 = __float2bfloat16(v1.w);
            __nv_bfloat162 hp0(h0, h1), hp1(h2, h3), hp2(h4, h5), hp3(h6, h7);
            __nv_bfloat162 lp0(__float2bfloat16(v0.x - __bfloat162float(h0)),
                               __float2bfloat16(v0.y - __bfloat162float(h1)));
            __nv_bfloat162 lp1(__float2bfloat16(v0.z - __bfloat162float(h2)),
                               __float2bfloat16(v0.w - __bfloat162float(h3)));
            __nv_bfloat162 lp2(__float2bfloat16(v1.x - __bfloat162float(h4)),
                               __float2bfloat16(v1.y - __bfloat162float(h5)));
            __nv_bfloat162 lp3(__float2bfloat16(v1.z - __bfloat162float(h6)),
                               __float2bfloat16(v1.w - __bfloat162float(h7)));
            uint4 hv = make_uint4(*(uint32_t*)&hp0, *(uint32_t*)&hp1,
                                  *(uint32_t*)&hp2, *(uint32_t*)&hp3);
            uint4 lv = make_uint4(*(uint32_t*)&lp0, *(uint32_t*)&lp1,
                                  *(uint32_t*)&lp2, *(uint32_t*)&lp3);
            *(uint4*)&xh32[cbase32 + i * 4] = hv;
            *(uint4*)&xl32[cbase32 + i * 4] = lv;
        }
        __syncthreads();           // Xhi/lo ready; stage free

        // ---- prefetch next tile (overlaps mainloop) ----
        {
            int tn = t + gridDim.x;
            if (tn < NTILES) {
                int gr = tn * 128 + pr;
                if (gr < NN) {
                    const float* srcp = &xin[(size_t)gr * 128 + ph * 32];
                    #pragma unroll
                    for (int i = 0; i < 8; i++) CP_ASYNC16(pdst + i * 16, srcp + i * 4);
                } else {
                    float4 z = make_float4(0.f, 0.f, 0.f, 0.f);
                    #pragma unroll
                    for (int i = 0; i < 8; i++)
                        *(float4*)(sm + ST_OFF + (pr * SSTRIDE + ph * 32) * 4 + i * 16) = z;
                }
            }
            CP_COMMIT();
        }

        // ---- mainloop: 8 k-steps of 16, TERM-MAJOR MMA order ----
        float acc[2][NFRAG][4];
        #pragma unroll
        for (int mi = 0; mi < 2; mi++)
            #pragma unroll
            for (int f = 0; f < NFRAG; f++)
                #pragma unroll
                for (int q = 0; q < 4; q++) acc[mi][f][q] = 0.f;

        uint32_t aH = aH0, aL = aH0 + XL_OFF, bH = bH0, bL = bH0 + WBYTES;
        #pragma unroll
        for (int ks = 0; ks < 8; ks++) {
            uint32_t AH[2][4], AL[2][4];
            LDSM4(AH[0], aH);
            LDSM4(AH[1], aH + 16 * XS * 2);
            LDSM4(AL[0], aL);
            LDSM4(AL[1], aL + 16 * XS * 2);
            uint32_t BH[NF2][4], BL[NF2][4];
            #pragma unroll
            for (int j = 0; j < NF2; j++) {
                LDSM4(BH[j], bH + j * 16 * XS * 2);
                LDSM4(BL[j], bL + j * 16 * XS * 2);
            }
            // term 0: AH x BH  (all accumulators independent)
            #pragma unroll
            for (int mi = 0; mi < 2; mi++)
                #pragma unroll
                for (int j = 0; j < NF2; j++)
                    #pragma unroll
                    for (int h = 0; h < 2; h++)
                        MMA_BF16(acc[mi][j * 2 + h], AH[mi],
                                 BH[j][h * 2], BH[j][h * 2 + 1]);
            // term 1: AL x BH
            #pragma unroll
            for (int mi = 0; mi < 2; mi++)
                #pragma unroll
                for (int j = 0; j < NF2; j++)
                    #pragma unroll
                    for (int h = 0; h < 2; h++)
                        MMA_BF16(acc[mi][j * 2 + h], AL[mi],
                                 BH[j][h * 2], BH[j][h * 2 + 1]);
            // term 2: AH x BL
            #pragma unroll
            for (int mi = 0; mi < 2; mi++)
                #pragma unroll
                for (int j = 0; j < NF2; j++)
                    #pragma unroll
                    for (int h = 0; h < 2; h++)
                        MMA_BF16(acc[mi][j * 2 + h], AH[mi],
                                 BL[j][h * 2], BL[j][h * 2 + 1]);
            aH += 32; aL += 32; bH += 32; bL += 32;
        }

        // ---- epilogue: scale by norm_out, store fp16 ----
        #pragma unroll
        for (int mi = 0; mi < 2; mi++) {
            int r1 = row0 + m0 + mi * 16 + g;
            int r2 = r1 + 8;
            float s1 = (r1 < NN) ? g_norm_out[r1] : 0.f;
            float s2 = (r2 < NN) ? g_norm_out[r2] : 0.f;
            #pragma unroll
            for (int f = 0; f < NFRAG; f++) {
                int n = n0 + f * 8 + tq * 2;
                if (OUTC < NTILE && n >= OUTC) continue;
                float* c = acc[mi][f];
                if (r1 < NN) {
                    __half2 hv = __floats2half2_rn(c[0] * s1, c[1] * s1);
                    *(__half2*)&hout[(size_t)r1 * OUTC + n] = hv;
                }
                if (r2 < NN) {
                    __half2 hv = __floats2half2_rn(c[2] * s2, c[3] * s2);
                    *(__half2*)&hout[(size_t)r2 * OUTC + n] = hv;
                }
            }
        }
    }
}

// ===========================================================================
// Aggregation 128-dim: one warp per dst node; CSR gather (fp16), fp32 accum.
// ===========================================================================
template <int RELU>
__global__ void __launch_bounds__(256)
agg128(const float* __restrict__ bias) {
    int w = (blockIdx.x * blockDim.x + threadIdx.x) >> 5;
    if (w >= NN) return;
    int lane = threadIdx.x & 31;
    int beg = g_offs[w], end = g_offs[w + 1];

    float4 acc = make_float4(0.f, 0.f, 0.f, 0.f);
    int e = beg;
    for (; e + 4 <= end; e += 4) {
        int s0 = g_csr[e],     s1 = g_csr[e + 1];
        int s2 = g_csr[e + 2], s3 = g_csr[e + 3];
        uint2 u0 = *(const uint2*)&g_hbuf[(size_t)s0 * 128 + lane * 4];
        uint2 u1 = *(const uint2*)&g_hbuf[(size_t)s1 * 128 + lane * 4];
        uint2 u2 = *(const uint2*)&g_hbuf[(size_t)s2 * 128 + lane * 4];
        uint2 u3 = *(const uint2*)&g_hbuf[(size_t)s3 * 128 + lane * 4];
        float2 a0 = __half22float2(*(__half2*)&u0.x), b0 = __half22float2(*(__half2*)&u0.y);
        float2 a1 = __half22float2(*(__half2*)&u1.x), b1 = __half22float2(*(__half2*)&u1.y);
        float2 a2 = __half22float2(*(__half2*)&u2.x), b2 = __half22float2(*(__half2*)&u2.y);
        float2 a3 = __half22float2(*(__half2*)&u3.x), b3 = __half22float2(*(__half2*)&u3.y);
        acc.x += (a0.x + a1.x) + (a2.x + a3.x);
        acc.y += (a0.y + a1.y) + (a2.y + a3.y);
        acc.z += (b0.x + b1.x) + (b2.x + b3.x);
        acc.w += (b0.y + b1.y) + (b2.y + b3.y);
    }
    for (; e < end; e++) {
        int s0 = g_csr[e];
        uint2 u0 = *(const uint2*)&g_hbuf[(size_t)s0 * 128 + lane * 4];
        float2 a0 = __half22float2(*(__half2*)&u0.x), b0 = __half22float2(*(__half2*)&u0.y);
        acc.x += a0.x; acc.y += a0.y; acc.z += b0.x; acc.w += b0.y;
    }

    float sc = g_norm_in[w];
    float4 b = *(const float4*)&bias[lane * 4];
    float4 o;
    o.x = fmaf(acc.x, sc, b.x);
    o.y = fmaf(acc.y, sc, b.y);
    o.z = fmaf(acc.z, sc, b.z);
    o.w = fmaf(acc.w, sc, b.w);
    if (RELU) {
        o.x = fmaxf(o.x, 0.f); o.y = fmaxf(o.y, 0.f);
        o.z = fmaxf(o.z, 0.f); o.w = fmaxf(o.w, 0.f);
    }
    *(float4*)&g_bufB[(size_t)w * 128 + lane * 4] = o;
}

// ===========================================================================
// Aggregation 40-dim (final layer, no relu) -> d_out (fp32)
// ===========================================================================
__global__ void __launch_bounds__(256)
agg40(const float* __restrict__ bias, float* __restrict__ out) {
    int w = (blockIdx.x * blockDim.x + threadIdx.x) >> 5;
    if (w >= NN) return;
    int lane = threadIdx.x & 31;
    int beg = g_offs[w], end = g_offs[w + 1];
    if (lane >= 20) return;

    float2 acc = make_float2(0.f, 0.f);
    int e = beg;
    for (; e + 2 <= end; e += 2) {
        int s0 = g_csr[e], s1 = g_csr[e + 1];
        __half2 h0 = *(const __half2*)&g_hbuf[(size_t)s0 * 40 + lane * 2];
        __half2 h1 = *(const __half2*)&g_hbuf[(size_t)s1 * 40 + lane * 2];
        float2 f0 = __half22float2(h0);
        float2 f1 = __half22float2(h1);
        acc.x += f0.x + f1.x;
        acc.y += f0.y + f1.y;
    }
    if (e < end) {
        int s0 = g_csr[e];
        float2 f0 = __half22float2(*(const __half2*)&g_hbuf[(size_t)s0 * 40 + lane * 2]);
        acc.x += f0.x; acc.y += f0.y;
    }
    float sc = g_norm_in[w];
    float2 o;
    o.x = fmaf(acc.x, sc, bias[lane * 2]);
    o.y = fmaf(acc.y, sc, bias[lane * 2 + 1]);
    *(float2*)&out[(size_t)w * 40 + lane * 2] = o;
}

// ===========================================================================
extern "C" void kernel_launch(void* const* d_in, const int* in_sizes, int n_in,
                              void* d_out, int out_size) {
    const float* feat = (const float*)d_in[0];
    const int*   src  = (const int*)  d_in[1];
    const int*   dst  = (const int*)  d_in[2];
    const float* W0   = (const float*)d_in[3];
    const float* b0   = (const float*)d_in[4];
    const float* W1   = (const float*)d_in[5];
    const float* b1   = (const float*)d_in[6];
    const float* W2   = (const float*)d_in[7];
    const float* b2   = (const float*)d_in[8];
    float* out = (float*)d_out;

    const int NB = (NN + 255) / 256;
    const int EB = (EE + 255) / 256;
    const int SB = (NN + 1023) / 1024;
    const int AGGB = (NN * 32 + 255) / 256;

    // smem: Xhi/lo 69632 + W(hi+lo) + stage 128*132*4=67584
    const int SMEM_BIG   = 69632 + 2 * 128 * 136 * 2 + 67584;  // 206848
    const int SMEM_SMALL = 69632 + 2 * 64 * 136 * 2 + 67584;   // 172032
    static bool attr_done = false;
    if (!attr_done) {
        cudaFuncSetAttribute(gemm_pers<128, 128>,
                             cudaFuncAttributeMaxDynamicSharedMemorySize, SMEM_BIG);
        cudaFuncSetAttribute(gemm_pers<64, 40>,
                             cudaFuncAttributeMaxDynamicSharedMemorySize, SMEM_SMALL);
        attr_done = true;
    }

    unsigned char *p_B0h, *p_B0l, *p_B1h, *p_B1l, *p_B2h, *p_B2l;
    cudaGetSymbolAddress((void**)&p_B0h, g_B0h);
    cudaGetSymbolAddress((void**)&p_B0l, g_B0l);
    cudaGetSymbolAddress((void**)&p_B1h, g_B1h);
    cudaGetSymbolAddress((void**)&p_B1l, g_B1l);
    cudaGetSymbolAddress((void**)&p_B2h, g_B2h);
    cudaGetSymbolAddress((void**)&p_B2l, g_B2l);
    __half* p_hbuf;
    float*  p_bufB;
    cudaGetSymbolAddress((void**)&p_hbuf, g_hbuf);
    cudaGetSymbolAddress((void**)&p_bufB, g_bufB);

    // prep (gemm layer-0 kept at launch index 3 for ncu sampling)
    k_zero<<<NB, 256>>>();                               // 0
    k_deg<<<EB, 256>>>(src, dst);                        // 1
    k_norm_wtiles<<<NB, 256>>>(W0, W1, W2);              // 2
    gemm_pers<128, 128><<<PGRID, 512, SMEM_BIG>>>(       // 3 (layer 0 GEMM)
        feat, p_B0h, p_B0l, p_hbuf);
    k_scan1<<<SB, 1024>>>();                             // 4
    k_scan2<<<1, 128>>>(SB);                             // 5
    k_scan3<<<NB, 256>>>();                              // 6
    k_scatter<<<EB, 256>>>(src, dst);                    // 7

    // layer 0 aggregation
    agg128<1><<<AGGB, 256>>>(b0);
    // layer 1
    gemm_pers<128, 128><<<PGRID, 512, SMEM_BIG>>>(p_bufB, p_B1h, p_B1l, p_hbuf);
    agg128<1><<<AGGB, 256>>>(b1);
    // layer 2
    gemm_pers<64, 40><<<PGRID, 512, SMEM_SMALL>>>(p_bufB, p_B2h, p_B2l, p_hbuf);
    agg40<<<AGGB, 256>>>(b2, out);
}

// round 9
// speedup vs baseline: 1.0485x; 1.0148x over previous
#include <cuda_runtime.h>
#include <cuda_bf16.h>
#include <cuda_fp16.h>
#include <math.h>
#include <stdint.h>

#define NN 100000
#define EE 1600000
#define HD 128
#define CD 40
#define NTILES 782            // ceil(NN/128)
#define PGRID 148             // persistent grid (1 CTA/SM)

// -------- scratch (static __device__ arrays; allocation forbidden) --------
__device__ __half g_hbuf[(size_t)NN * HD];  // 25.6 MB : GEMM out (gather src)
__device__ float  g_bufB[(size_t)NN * HD];  // 51.2 MB : agg out (GEMM in)
__device__ int    g_deg_out[NN];
__device__ int    g_deg_in[NN];
__device__ float  g_norm_out[NN];
__device__ float  g_norm_in[NN];
__device__ int    g_offs[NN + 1];
__device__ int    g_cursor[NN];
__device__ int    g_bsums[128];
__device__ int    g_csr[EE];                // 6.4 MB

// Pre-built W operand tiles: [n][k] bf16, padded row stride 136 elems, hi/lo.
__device__ __align__(16) unsigned char g_B0h[128 * 136 * 2];
__device__ __align__(16) unsigned char g_B0l[128 * 136 * 2];
__device__ __align__(16) unsigned char g_B1h[128 * 136 * 2];
__device__ __align__(16) unsigned char g_B1l[128 * 136 * 2];
__device__ __align__(16) unsigned char g_B2h[64 * 136 * 2];
__device__ __align__(16) unsigned char g_B2l[64 * 136 * 2];

// ===========================================================================
// helpers (baseline sm_80 features -- no 'a'-gated PTX)
// ===========================================================================
__device__ __forceinline__ uint32_t smem_to_u32(const void* p) {
    uint32_t a;
    asm("{ .reg .u64 t; cvta.to.shared.u64 t, %1; cvt.u32.u64 %0, t; }"
        : "=r"(a) : "l"(p));
    return a;
}

#define LDSM4(r, addr) \
    asm volatile("ldmatrix.sync.aligned.m8n8.x4.shared.b16 {%0,%1,%2,%3}, [%4];" \
        : "=r"((r)[0]), "=r"((r)[1]), "=r"((r)[2]), "=r"((r)[3]) : "r"(addr))

#define MMA_BF16(d, a, b0, b1) \
    asm volatile("mma.sync.aligned.m16n8k16.row.col.f32.bf16.bf16.f32 " \
        "{%0,%1,%2,%3}, {%4,%5,%6,%7}, {%8,%9}, {%0,%1,%2,%3};" \
        : "+f"((d)[0]), "+f"((d)[1]), "+f"((d)[2]), "+f"((d)[3]) \
        : "r"((a)[0]), "r"((a)[1]), "r"((a)[2]), "r"((a)[3]), "r"(b0), "r"(b1))

#define CP_ASYNC16(dst_u32, src_ptr) \
    asm volatile("cp.async.cg.shared.global [%0], [%1], 16;" \
        :: "r"(dst_u32), "l"(src_ptr) : "memory")
#define CP_COMMIT() asm volatile("cp.async.commit_group;" ::: "memory")
#define CP_WAIT0()  asm volatile("cp.async.wait_group 0;" ::: "memory")

// ===========================================================================
// Degrees + norms + CSR build
// ===========================================================================
__global__ void k_zero() {
    int i = blockIdx.x * blockDim.x + threadIdx.x;
    if (i < NN) { g_deg_out[i] = 0; g_deg_in[i] = 0; g_cursor[i] = 0; }
}

__global__ void k_deg(const int* __restrict__ src, const int* __restrict__ dst) {
    int e = blockIdx.x * blockDim.x + threadIdx.x;
    if (e < EE) {
        atomicAdd(&g_deg_out[src[e]], 1);
        atomicAdd(&g_deg_in[dst[e]], 1);
    }
}

// Fused: per-node norms + W-tile build ([n][k] bf16 hi/lo, stride 136)
__global__ void k_norm_wtiles(const float* __restrict__ W0,
                              const float* __restrict__ W1,
                              const float* __restrict__ W2) {
    int i = blockIdx.x * blockDim.x + threadIdx.x;
    if (i < NN) {
        int d0 = g_deg_out[i];
        int d1 = g_deg_in[i];
        g_norm_out[i] = d0 > 0 ? rsqrtf((float)d0) : 0.f;
        g_norm_in[i]  = d1 > 0 ? rsqrtf((float)d1) : 0.f;
    }
    if (i < 40960) {
        float val;
        unsigned char *ph, *pl;
        int n, k;
        if (i < 32768) {
            const float* W = (i < 16384) ? W0 : W1;
            ph = (i < 16384) ? g_B0h : g_B1h;
            pl = (i < 16384) ? g_B0l : g_B1l;
            int e = i & 16383;
            n = e >> 7; k = e & 127;
            val = W[k * 128 + n];
        } else {
            int e = i - 32768;
            n = e >> 7; k = e & 127;      // n in [0,64)
            val = (n < CD) ? W2[k * CD + n] : 0.f;
            ph = g_B2h; pl = g_B2l;
        }
        __nv_bfloat16 hi = __float2bfloat16(val);
        __nv_bfloat16 lo = __float2bfloat16(val - __bfloat162float(hi));
        uint32_t off = ((uint32_t)n * 136u + (uint32_t)k) * 2u;
        *(__nv_bfloat16*)(ph + off) = hi;
        *(__nv_bfloat16*)(pl + off) = lo;
    }
}

__global__ void k_scan1() {
    __shared__ int sh[1024];
    int i = blockIdx.x * 1024 + threadIdx.x;
    int v = (i < NN) ? g_deg_in[i] : 0;
    sh[threadIdx.x] = v;
    __syncthreads();
    #pragma unroll
    for (int d = 1; d < 1024; d <<= 1) {
        int t = 0;
        if ((int)threadIdx.x >= d) t = sh[threadIdx.x - d];
        __syncthreads();
        sh[threadIdx.x] += t;
        __syncthreads();
    }
    if (i < NN) g_offs[i + 1] = sh[threadIdx.x];
    if (threadIdx.x == 1023) g_bsums[blockIdx.x] = sh[1023];
}

// Parallel exclusive scan of block sums (nb <= 128), one block.
__global__ void k_scan2(int nb) {
    __shared__ int sh[128];
    int t = threadIdx.x;
    int v = (t < nb) ? g_bsums[t] : 0;
    sh[t] = v;
    __syncthreads();
    #pragma unroll
    for (int d = 1; d < 128; d <<= 1) {
        int x = 0;
        if (t >= d) x = sh[t - d];
        __syncthreads();
        sh[t] += x;
        __syncthreads();
    }
    if (t < nb) g_bsums[t] = sh[t] - v;   // exclusive
}

__global__ void k_scan3() {
    int i = blockIdx.x * blockDim.x + threadIdx.x;
    if (i == 0) g_offs[0] = 0;
    if (i < NN) g_offs[i + 1] += g_bsums[i >> 10];
}

__global__ void k_scatter(const int* __restrict__ src, const int* __restrict__ dst) {
    int e = blockIdx.x * blockDim.x + threadIdx.x;
    if (e < EE) {
        int d = dst[e];
        int pos = g_offs[d] + atomicAdd(&g_cursor[d], 1);
        g_csr[pos] = src[e];
    }
}

// ===========================================================================
// Persistent HMMA GEMM: hout[r,0:OUTC] = fp16(norm_out[r] * (x[r,:] @ W))
// grid=PGRID, 512 threads (16 warps, 4/SMSP). W resident in smem; X tiles
// stream via cp.async. Warp tile 32m x (NTILE/4)n. 3-term bf16 emulation,
// term-major MMA order + EXPLICIT k-step fragment double-buffering.
// ===========================================================================
template <int NTILE, int OUTC>
__global__ void __launch_bounds__(512)
gemm_pers(const float* __restrict__ xin,
          const unsigned char* __restrict__ Wh,
          const unsigned char* __restrict__ Wl,
          __half* __restrict__ hout) {
    extern __shared__ __align__(16) unsigned char sm[];
    constexpr int XS      = 136;                   // bf16 row stride (elems)
    constexpr int SSTRIDE = 132;                   // stage row stride (floats)
    constexpr int XH_OFF  = 0;
    constexpr int XL_OFF  = 128 * XS * 2;          // 34816
    constexpr int WH_OFF  = XL_OFF * 2;            // 69632
    constexpr int WBYTES  = NTILE * XS * 2;
    constexpr int WL_OFF  = WH_OFF + WBYTES;
    constexpr int ST_OFF  = WL_OFF + WBYTES;
    constexpr int NWTILE  = NTILE / 4;             // warp n-tile (32 or 16)
    constexpr int NFRAG   = NWTILE / 8;            // n8 frags (4 or 2)
    constexpr int NF2     = NFRAG / 2;             // LDSM.x4 count (2 or 1)

    const int tid  = threadIdx.x;
    const int wid  = tid >> 5;
    const int lane = tid & 31;

    const uint32_t smb    = smem_to_u32(sm);
    const uint32_t st_smb = smb + ST_OFF;

    // prefetch lane mapping: 4 threads/row, 32 floats (8 x 16B) each
    const int pr = tid >> 2;
    const int ph = tid & 3;
    const uint32_t pdst = st_smb + (uint32_t)((pr * SSTRIDE + ph * 32) * 4);

    // ---- issue prefetch for first tile ----
    {
        int gr = blockIdx.x * 128 + pr;
        if (gr < NN) {
            const float* srcp = &xin[(size_t)gr * 128 + ph * 32];
            #pragma unroll
            for (int i = 0; i < 8; i++) CP_ASYNC16(pdst + i * 16, srcp + i * 4);
        } else {
            float4 z = make_float4(0.f, 0.f, 0.f, 0.f);
            #pragma unroll
            for (int i = 0; i < 8; i++)
                *(float4*)(sm + ST_OFF + (pr * SSTRIDE + ph * 32) * 4 + i * 16) = z;
        }
        CP_COMMIT();
    }

    // ---- W: copy once (overlaps with in-flight cp.async) ----
    {
        const float4* s4h = (const float4*)Wh;
        const float4* s4l = (const float4*)Wl;
        float4* d4h = (float4*)(sm + WH_OFF);
        float4* d4l = (float4*)(sm + WL_OFF);
        for (int i = tid; i < WBYTES / 16; i += 512) {
            d4h[i] = s4h[i];
            d4l[i] = s4l[i];
        }
    }

    // per-lane ldmatrix base offsets (constant across tiles)
    const int m0 = (wid & 3) * 32;
    const int n0 = (wid >> 2) * NWTILE;
    const uint32_t aH0 = smb + XH_OFF +
        (uint32_t)(((m0 + (lane & 15)) * XS + (lane >> 4) * 8) * 2);
    const uint32_t bH0 = smb + WH_OFF +
        (uint32_t)(((n0 + (lane >> 4) * 8 + (lane & 7)) * XS + ((lane >> 3) & 1) * 8) * 2);

    // convert lane mapping: 4 threads/row, 32 floats each (k-quarter)
    const int cr = tid & 127;
    const int ch = tid >> 7;               // 0..3 -> k-quarter
    const float4* stage4 = (const float4*)(sm + ST_OFF);
    const int sbase4 = cr * (SSTRIDE / 4) + ch * 8;
    uint32_t* xh32 = (uint32_t*)(sm + XH_OFF);
    uint32_t* xl32 = (uint32_t*)(sm + XL_OFF);
    const int cbase32 = (cr * XS + ch * 32) >> 1;

    const int g  = lane >> 2;
    const int tq = lane & 3;

    for (int t = blockIdx.x; t < NTILES; t += gridDim.x) {
        const int row0 = t * 128;

        CP_WAIT0();
        __syncthreads();           // stage ready; prev mainloop fully done

        // ---- convert stage (fp32) -> Xhi/Xlo (bf16) in smem ----
        #pragma unroll
        for (int i = 0; i < 4; i++) {
            float4 v0 = stage4[sbase4 + i * 2];
            float4 v1 = stage4[sbase4 + i * 2 + 1];
            __nv_bfloat16 h0 = __float2bfloat16(v0.x), h1 = __float2bfloat16(v0.y);
            __nv_bfloat16 h2 = __float2bfloat16(v0.z), h3 = __float2bfloat16(v0.w);
            __nv_bfloat16 h4 = __float2bfloat16(v1.x), h5 = __float2bfloat16(v1.y);
            __nv_bfloat16 h6 = __float2bfloat16(v1.z), h7 = __float2bfloat16(v1.w);
            __nv_bfloat162 hp0(h0, h1), hp1(h2, h3), hp2(h4, h5), hp3(h6, h7);
            __nv_bfloat162 lp0(__float2bfloat16(v0.x - __bfloat162float(h0)),
                               __float2bfloat16(v0.y - __bfloat162float(h1)));
            __nv_bfloat162 lp1(__float2bfloat16(v0.z - __bfloat162float(h2)),
                               __float2bfloat16(v0.w - __bfloat162float(h3)));
            __nv_bfloat162 lp2(__float2bfloat16(v1.x - __bfloat162float(h4)),
                               __float2bfloat16(v1.y - __bfloat162float(h5)));
            __nv_bfloat162 lp3(__float2bfloat16(v1.z - __bfloat162float(h6)),
                               __float2bfloat16(v1.w - __bfloat162float(h7)));
            uint4 hv = make_uint4(*(uint32_t*)&hp0, *(uint32_t*)&hp1,
                                  *(uint32_t*)&hp2, *(uint32_t*)&hp3);
            uint4 lv = make_uint4(*(uint32_t*)&lp0, *(uint32_t*)&lp1,
                                  *(uint32_t*)&lp2, *(uint32_t*)&lp3);
            *(uint4*)&xh32[cbase32 + i * 4] = hv;
            *(uint4*)&xl32[cbase32 + i * 4] = lv;
        }
        __syncthreads();           // Xhi/lo ready; stage free

        // ---- prefetch next tile (overlaps mainloop) ----
        {
            int tn = t + gridDim.x;
            if (tn < NTILES) {
                int gr = tn * 128 + pr;
                if (gr < NN) {
                    const float* srcp = &xin[(size_t)gr * 128 + ph * 32];
                    #pragma unroll
                    for (int i = 0; i < 8; i++) CP_ASYNC16(pdst + i * 16, srcp + i * 4);
                } else {
                    float4 z = make_float4(0.f, 0.f, 0.f, 0.f);
                    #pragma unroll
                    for (int i = 0; i < 8; i++)
                        *(float4*)(sm + ST_OFF + (pr * SSTRIDE + ph * 32) * 4 + i * 16) = z;
                }
            }
            CP_COMMIT();
        }

        // ---- mainloop: 8 k-steps, fragment double-buffer, term-major ----
        float acc[2][NFRAG][4];
        #pragma unroll
        for (int mi = 0; mi < 2; mi++)
            #pragma unroll
            for (int f = 0; f < NFRAG; f++)
                #pragma unroll
                for (int q = 0; q < 4; q++) acc[mi][f][q] = 0.f;

        uint32_t AHf[2][2][4], ALf[2][2][4];
        uint32_t BHf[2][NF2][4], BLf[2][NF2][4];

        uint32_t aH = aH0, aL = aH0 + XL_OFF, bH = bH0, bL = bH0 + WBYTES;
        // preload k-step 0 fragments into buffer 0
        LDSM4(AHf[0][0], aH);
        LDSM4(AHf[0][1], aH + 16 * XS * 2);
        LDSM4(ALf[0][0], aL);
        LDSM4(ALf[0][1], aL + 16 * XS * 2);
        #pragma unroll
        for (int j = 0; j < NF2; j++) {
            LDSM4(BHf[0][j], bH + j * 16 * XS * 2);
            LDSM4(BLf[0][j], bL + j * 16 * XS * 2);
        }

        #pragma unroll
        for (int ks = 0; ks < 8; ks++) {
            const int cur = ks & 1;
            const int nxt = cur ^ 1;
            if (ks < 7) {
                aH += 32; aL += 32; bH += 32; bL += 32;
                LDSM4(AHf[nxt][0], aH);
                LDSM4(AHf[nxt][1], aH + 16 * XS * 2);
                LDSM4(ALf[nxt][0], aL);
                LDSM4(ALf[nxt][1], aL + 16 * XS * 2);
                #pragma unroll
                for (int j = 0; j < NF2; j++) {
                    LDSM4(BHf[nxt][j], bH + j * 16 * XS * 2);
                    LDSM4(BLf[nxt][j], bL + j * 16 * XS * 2);
                }
            }
            // term 0: AH x BH  (independent accumulators)
            #pragma unroll
            for (int mi = 0; mi < 2; mi++)
                #pragma unroll
                for (int j = 0; j < NF2; j++)
                    #pragma unroll
                    for (int h = 0; h < 2; h++)
                        MMA_BF16(acc[mi][j * 2 + h], AHf[cur][mi],
                                 BHf[cur][j][h * 2], BHf[cur][j][h * 2 + 1]);
            // term 1: AL x BH
            #pragma unroll
            for (int mi = 0; mi < 2; mi++)
                #pragma unroll
                for (int j = 0; j < NF2; j++)
                    #pragma unroll
                    for (int h = 0; h < 2; h++)
                        MMA_BF16(acc[mi][j * 2 + h], ALf[cur][mi],
                                 BHf[cur][j][h * 2], BHf[cur][j][h * 2 + 1]);
            // term 2: AH x BL
            #pragma unroll
            for (int mi = 0; mi < 2; mi++)
                #pragma unroll
                for (int j = 0; j < NF2; j++)
                    #pragma unroll
                    for (int h = 0; h < 2; h++)
                        MMA_BF16(acc[mi][j * 2 + h], AHf[cur][mi],
                                 BLf[cur][j][h * 2], BLf[cur][j][h * 2 + 1]);
        }

        // ---- epilogue: scale by norm_out, store fp16 ----
        #pragma unroll
        for (int mi = 0; mi < 2; mi++) {
            int r1 = row0 + m0 + mi * 16 + g;
            int r2 = r1 + 8;
            float s1 = (r1 < NN) ? g_norm_out[r1] : 0.f;
            float s2 = (r2 < NN) ? g_norm_out[r2] : 0.f;
            #pragma unroll
            for (int f = 0; f < NFRAG; f++) {
                int n = n0 + f * 8 + tq * 2;
                if (OUTC < NTILE && n >= OUTC) continue;
                float* c = acc[mi][f];
                if (r1 < NN) {
                    __half2 hv = __floats2half2_rn(c[0] * s1, c[1] * s1);
                    *(__half2*)&hout[(size_t)r1 * OUTC + n] = hv;
                }
                if (r2 < NN) {
                    __half2 hv = __floats2half2_rn(c[2] * s2, c[3] * s2);
                    *(__half2*)&hout[(size_t)r2 * OUTC + n] = hv;
                }
            }
        }
    }
}

// ===========================================================================
// Aggregation 128-dim: one warp per dst node; CSR gather (fp16), fp32 accum.
// ===========================================================================
template <int RELU>
__global__ void __launch_bounds__(256)
agg128(const float* __restrict__ bias) {
    int w = (blockIdx.x * blockDim.x + threadIdx.x) >> 5;
    if (w >= NN) return;
    int lane = threadIdx.x & 31;
    int beg = g_offs[w], end = g_offs[w + 1];

    float4 acc = make_float4(0.f, 0.f, 0.f, 0.f);
    int e = beg;
    for (; e + 4 <= end; e += 4) {
        int s0 = g_csr[e],     s1 = g_csr[e + 1];
        int s2 = g_csr[e + 2], s3 = g_csr[e + 3];
        uint2 u0 = *(const uint2*)&g_hbuf[(size_t)s0 * 128 + lane * 4];
        uint2 u1 = *(const uint2*)&g_hbuf[(size_t)s1 * 128 + lane * 4];
        uint2 u2 = *(const uint2*)&g_hbuf[(size_t)s2 * 128 + lane * 4];
        uint2 u3 = *(const uint2*)&g_hbuf[(size_t)s3 * 128 + lane * 4];
        float2 a0 = __half22float2(*(__half2*)&u0.x), b0 = __half22float2(*(__half2*)&u0.y);
        float2 a1 = __half22float2(*(__half2*)&u1.x), b1 = __half22float2(*(__half2*)&u1.y);
        float2 a2 = __half22float2(*(__half2*)&u2.x), b2 = __half22float2(*(__half2*)&u2.y);
        float2 a3 = __half22float2(*(__half2*)&u3.x), b3 = __half22float2(*(__half2*)&u3.y);
        acc.x += (a0.x + a1.x) + (a2.x + a3.x);
        acc.y += (a0.y + a1.y) + (a2.y + a3.y);
        acc.z += (b0.x + b1.x) + (b2.x + b3.x);
        acc.w += (b0.y + b1.y) + (b2.y + b3.y);
    }
    for (; e < end; e++) {
        int s0 = g_csr[e];
        uint2 u0 = *(const uint2*)&g_hbuf[(size_t)s0 * 128 + lane * 4];
        float2 a0 = __half22float2(*(__half2*)&u0.x), b0 = __half22float2(*(__half2*)&u0.y);
        acc.x += a0.x; acc.y += a0.y; acc.z += b0.x; acc.w += b0.y;
    }

    float sc = g_norm_in[w];
    float4 b = *(const float4*)&bias[lane * 4];
    float4 o;
    o.x = fmaf(acc.x, sc, b.x);
    o.y = fmaf(acc.y, sc, b.y);
    o.z = fmaf(acc.z, sc, b.z);
    o.w = fmaf(acc.w, sc, b.w);
    if (RELU) {
        o.x = fmaxf(o.x, 0.f); o.y = fmaxf(o.y, 0.f);
        o.z = fmaxf(o.z, 0.f); o.w = fmaxf(o.w, 0.f);
    }
    *(float4*)&g_bufB[(size_t)w * 128 + lane * 4] = o;
}

// ===========================================================================
// Aggregation 40-dim (final layer, no relu) -> d_out (fp32)
// ===========================================================================
__global__ void __launch_bounds__(256)
agg40(const float* __restrict__ bias, float* __restrict__ out) {
    int w = (blockIdx.x * blockDim.x + threadIdx.x) >> 5;
    if (w >= NN) return;
    int lane = threadIdx.x & 31;
    int beg = g_offs[w], end = g_offs[w + 1];
    if (lane >= 20) return;

    float2 acc = make_float2(0.f, 0.f);
    int e = beg;
    for (; e + 2 <= end; e += 2) {
        int s0 = g_csr[e], s1 = g_csr[e + 1];
        __half2 h0 = *(const __half2*)&g_hbuf[(size_t)s0 * 40 + lane * 2];
        __half2 h1 = *(const __half2*)&g_hbuf[(size_t)s1 * 40 + lane * 2];
        float2 f0 = __half22float2(h0);
        float2 f1 = __half22float2(h1);
        acc.x += f0.x + f1.x;
        acc.y += f0.y + f1.y;
    }
    if (e < end) {
        int s0 = g_csr[e];
        float2 f0 = __half22float2(*(const __half2*)&g_hbuf[(size_t)s0 * 40 + lane * 2]);
        acc.x += f0.x; acc.y += f0.y;
    }
    float sc = g_norm_in[w];
    float2 o;
    o.x = fmaf(acc.x, sc, bias[lane * 2]);
    o.y = fmaf(acc.y, sc, bias[lane * 2 + 1]);
    *(float2*)&out[(size_t)w * 40 + lane * 2] = o;
}

// ===========================================================================
extern "C" void kernel_launch(void* const* d_in, const int* in_sizes, int n_in,
                              void* d_out, int out_size) {
    const float* feat = (const float*)d_in[0];
    const int*   src  = (const int*)  d_in[1];
    const int*   dst  = (const int*)  d_in[2];
    const float* W0   = (const float*)d_in[3];
    const float* b0   = (const float*)d_in[4];
    const float* W1   = (const float*)d_in[5];
    const float* b1   = (const float*)d_in[6];
    const float* W2   = (const float*)d_in[7];
    const float* b2   = (const float*)d_in[8];
    float* out = (float*)d_out;

    const int NB = (NN + 255) / 256;
    const int EB = (EE + 255) / 256;
    const int SB = (NN + 1023) / 1024;
    const int AGGB = (NN * 32 + 255) / 256;

    // smem: Xhi/lo 69632 + W(hi+lo) + stage 128*132*4=67584
    const int SMEM_BIG   = 69632 + 2 * 128 * 136 * 2 + 67584;  // 206848
    const int SMEM_SMALL = 69632 + 2 * 64 * 136 * 2 + 67584;   // 172032

    // one-time host-side resources (created on the uncaptured correctness
    // call; only reused -- never created -- during graph capture)
    static cudaStream_t s2 = nullptr;
    static cudaEvent_t evF = nullptr, evJ = nullptr;
    static bool init_done = false;
    if (!init_done) {
        cudaFuncSetAttribute(gemm_pers<128, 128>,
                             cudaFuncAttributeMaxDynamicSharedMemorySize, SMEM_BIG);
        cudaFuncSetAttribute(gemm_pers<64, 40>,
                             cudaFuncAttributeMaxDynamicSharedMemorySize, SMEM_SMALL);
        cudaStreamCreateWithFlags(&s2, cudaStreamNonBlocking);
        cudaEventCreateWithFlags(&evF, cudaEventDisableTiming);
        cudaEventCreateWithFlags(&evJ, cudaEventDisableTiming);
        init_done = true;
    }

    unsigned char *p_B0h, *p_B0l, *p_B1h, *p_B1l, *p_B2h, *p_B2l;
    cudaGetSymbolAddress((void**)&p_B0h, g_B0h);
    cudaGetSymbolAddress((void**)&p_B0l, g_B0l);
    cudaGetSymbolAddress((void**)&p_B1h, g_B1h);
    cudaGetSymbolAddress((void**)&p_B1l, g_B1l);
    cudaGetSymbolAddress((void**)&p_B2h, g_B2h);
    cudaGetSymbolAddress((void**)&p_B2l, g_B2l);
    __half* p_hbuf;
    float*  p_bufB;
    cudaGetSymbolAddress((void**)&p_hbuf, g_hbuf);
    cudaGetSymbolAddress((void**)&p_bufB, g_bufB);

    // common prep
    k_zero<<<NB, 256>>>();                               // 0
    k_deg<<<EB, 256>>>(src, dst);                        // 1
    k_norm_wtiles<<<NB, 256>>>(W0, W1, W2);              // 2

    // fork: layer-0 GEMM on s2 concurrent with CSR build on main stream
    cudaEventRecord(evF, 0);
    cudaStreamWaitEvent(s2, evF, 0);
    gemm_pers<128, 128><<<PGRID, 512, SMEM_BIG, s2>>>(   // 3 (layer 0 GEMM)
        feat, p_B0h, p_B0l, p_hbuf);
    k_scan1<<<SB, 1024>>>();                             // 4
    k_scan2<<<1, 128>>>(SB);                             // 5
    k_scan3<<<NB, 256>>>();                              // 6
    k_scatter<<<EB, 256>>>(src, dst);                    // 7
    cudaEventRecord(evJ, s2);
    cudaStreamWaitEvent(0, evJ, 0);

    // layer 0 aggregation
    agg128<1><<<AGGB, 256>>>(b0);
    // layer 1
    gemm_pers<128, 128><<<PGRID, 512, SMEM_BIG>>>(p_bufB, p_B1h, p_B1l, p_hbuf);
    agg128<1><<<AGGB, 256>>>(b1);
    // layer 2
    gemm_pers<64, 40><<<PGRID, 512, SMEM_SMALL>>>(p_bufB, p_B2h, p_B2l, p_hbuf);
    agg40<<<AGGB, 256>>>(b2, out);
}

// round 10
// speedup vs baseline: 1.0541x; 1.0054x over previous
#include <cuda_runtime.h>
#include <cuda_bf16.h>
#include <cuda_fp16.h>
#include <math.h>
#include <stdint.h>

#define NN 100000
#define EE 1600000
#define HD 128
#define CD 40
#define NTILES 782            // ceil(NN/128)
#define PGRID 148             // persistent grid (1 CTA/SM)

// -------- scratch (static __device__ arrays; allocation forbidden) --------
__device__ __half         g_hbuf[(size_t)NN * HD];  // GEMM out (gather src)
__device__ __nv_bfloat16  g_xh[(size_t)NN * HD];    // activation hi (GEMM in)
__device__ __nv_bfloat16  g_xl[(size_t)NN * HD];    // activation lo (GEMM in)
__device__ int    g_deg_out[NN];
__device__ int    g_deg_in[NN];
__device__ float  g_norm_out[NN];
__device__ float  g_norm_in[NN];
__device__ int    g_offs[NN + 1];
__device__ int    g_cursor[NN];
__device__ int    g_bsums[128];
__device__ int    g_csr[EE];

// Pre-built W operand tiles: [n][k] bf16, padded row stride 136 elems, hi/lo.
__device__ __align__(16) unsigned char g_B0h[128 * 136 * 2];
__device__ __align__(16) unsigned char g_B0l[128 * 136 * 2];
__device__ __align__(16) unsigned char g_B1h[128 * 136 * 2];
__device__ __align__(16) unsigned char g_B1l[128 * 136 * 2];
__device__ __align__(16) unsigned char g_B2h[64 * 136 * 2];
__device__ __align__(16) unsigned char g_B2l[64 * 136 * 2];

// ===========================================================================
// helpers (baseline sm_80 features -- no 'a'-gated PTX)
// ===========================================================================
__device__ __forceinline__ uint32_t smem_to_u32(const void* p) {
    uint32_t a;
    asm("{ .reg .u64 t; cvta.to.shared.u64 t, %1; cvt.u32.u64 %0, t; }"
        : "=r"(a) : "l"(p));
    return a;
}

#define LDSM4(r, addr) \
    asm volatile("ldmatrix.sync.aligned.m8n8.x4.shared.b16 {%0,%1,%2,%3}, [%4];" \
        : "=r"((r)[0]), "=r"((r)[1]), "=r"((r)[2]), "=r"((r)[3]) : "r"(addr))

#define MMA_BF16(d, a, b0, b1) \
    asm volatile("mma.sync.aligned.m16n8k16.row.col.f32.bf16.bf16.f32 " \
        "{%0,%1,%2,%3}, {%4,%5,%6,%7}, {%8,%9}, {%0,%1,%2,%3};" \
        : "+f"((d)[0]), "+f"((d)[1]), "+f"((d)[2]), "+f"((d)[3]) \
        : "r"((a)[0]), "r"((a)[1]), "r"((a)[2]), "r"((a)[3]), "r"(b0), "r"(b1))

#define CP_ASYNC16(dst_u32, src_ptr) \
    asm volatile("cp.async.cg.shared.global [%0], [%1], 16;" \
        :: "r"(dst_u32), "l"(src_ptr) : "memory")
#define CP_COMMIT() asm volatile("cp.async.commit_group;" ::: "memory")
#define CP_WAIT0()  asm volatile("cp.async.wait_group 0;" ::: "memory")

// split a float into bf16 hi/lo
__device__ __forceinline__ void bf16_split(float v, __nv_bfloat16& h, __nv_bfloat16& l) {
    h = __float2bfloat16(v);
    l = __float2bfloat16(v - __bfloat162float(h));
}

// ===========================================================================
// Degrees + norms + CSR build
// ===========================================================================
__global__ void k_zero() {
    int i = blockIdx.x * blockDim.x + threadIdx.x;
    if (i < NN) { g_deg_out[i] = 0; g_deg_in[i] = 0; g_cursor[i] = 0; }
}

__global__ void k_deg(const int* __restrict__ src, const int* __restrict__ dst) {
    int e = blockIdx.x * blockDim.x + threadIdx.x;
    if (e < EE) {
        atomicAdd(&g_deg_out[src[e]], 1);
        atomicAdd(&g_deg_in[dst[e]], 1);
    }
}

// Fused: per-node norms + W-tile build ([n][k] bf16 hi/lo, stride 136)
__global__ void k_norm_wtiles(const float* __restrict__ W0,
                              const float* __restrict__ W1,
                              const float* __restrict__ W2) {
    int i = blockIdx.x * blockDim.x + threadIdx.x;
    if (i < NN) {
        int d0 = g_deg_out[i];
        int d1 = g_deg_in[i];
        g_norm_out[i] = d0 > 0 ? rsqrtf((float)d0) : 0.f;
        g_norm_in[i]  = d1 > 0 ? rsqrtf((float)d1) : 0.f;
    }
    if (i < 40960) {
        float val;
        unsigned char *ph, *pl;
        int n, k;
        if (i < 32768) {
            const float* W = (i < 16384) ? W0 : W1;
            ph = (i < 16384) ? g_B0h : g_B1h;
            pl = (i < 16384) ? g_B0l : g_B1l;
            int e = i & 16383;
            n = e >> 7; k = e & 127;
            val = W[k * 128 + n];
        } else {
            int e = i - 32768;
            n = e >> 7; k = e & 127;      // n in [0,64)
            val = (n < CD) ? W2[k * CD + n] : 0.f;
            ph = g_B2h; pl = g_B2l;
        }
        __nv_bfloat16 hi, lo;
        bf16_split(val, hi, lo);
        uint32_t off = ((uint32_t)n * 136u + (uint32_t)k) * 2u;
        *(__nv_bfloat16*)(ph + off) = hi;
        *(__nv_bfloat16*)(pl + off) = lo;
    }
}

// Convert input features fp32 -> bf16 hi/lo buffers (one float4 per thread)
__global__ void k_feat(const float* __restrict__ feat) {
    size_t i = (size_t)blockIdx.x * blockDim.x + threadIdx.x;
    if (i >= (size_t)NN * 32) return;
    float4 v = ((const float4*)feat)[i];
    __nv_bfloat16 h0, h1, h2, h3, l0, l1, l2, l3;
    bf16_split(v.x, h0, l0); bf16_split(v.y, h1, l1);
    bf16_split(v.z, h2, l2); bf16_split(v.w, h3, l3);
    __nv_bfloat162 hp0(h0, h1), hp1(h2, h3), lp0(l0, l1), lp1(l2, l3);
    uint2 hv = make_uint2(*(uint32_t*)&hp0, *(uint32_t*)&hp1);
    uint2 lv = make_uint2(*(uint32_t*)&lp0, *(uint32_t*)&lp1);
    ((uint2*)g_xh)[i] = hv;
    ((uint2*)g_xl)[i] = lv;
}

__global__ void k_scan1() {
    __shared__ int sh[1024];
    int i = blockIdx.x * 1024 + threadIdx.x;
    int v = (i < NN) ? g_deg_in[i] : 0;
    sh[threadIdx.x] = v;
    __syncthreads();
    #pragma unroll
    for (int d = 1; d < 1024; d <<= 1) {
        int t = 0;
        if ((int)threadIdx.x >= d) t = sh[threadIdx.x - d];
        __syncthreads();
        sh[threadIdx.x] += t;
        __syncthreads();
    }
    if (i < NN) g_offs[i + 1] = sh[threadIdx.x];
    if (threadIdx.x == 1023) g_bsums[blockIdx.x] = sh[1023];
}

__global__ void k_scan2(int nb) {
    __shared__ int sh[128];
    int t = threadIdx.x;
    int v = (t < nb) ? g_bsums[t] : 0;
    sh[t] = v;
    __syncthreads();
    #pragma unroll
    for (int d = 1; d < 128; d <<= 1) {
        int x = 0;
        if (t >= d) x = sh[t - d];
        __syncthreads();
        sh[t] += x;
        __syncthreads();
    }
    if (t < nb) g_bsums[t] = sh[t] - v;   // exclusive
}

__global__ void k_scan3() {
    int i = blockIdx.x * blockDim.x + threadIdx.x;
    if (i == 0) g_offs[0] = 0;
    if (i < NN) g_offs[i + 1] += g_bsums[i >> 10];
}

__global__ void k_scatter(const int* __restrict__ src, const int* __restrict__ dst) {
    int e = blockIdx.x * blockDim.x + threadIdx.x;
    if (e < EE) {
        int d = dst[e];
        int pos = g_offs[d] + atomicAdd(&g_cursor[d], 1);
        g_csr[pos] = src[e];
    }
}

// ===========================================================================
// Persistent HMMA GEMM: hout[r,0:OUTC] = fp16(norm_out[r] * (x[r,:] @ W))
// X already in bf16 hi/lo in global -> cp.async straight into DOUBLE-BUFFERED
// smem; no convert phase, ONE barrier per tile. 512 thr, term-major 3-term.
// ===========================================================================
template <int NTILE, int OUTC>
__global__ void __launch_bounds__(512)
gemm_pers(const __nv_bfloat16* __restrict__ xh,
          const __nv_bfloat16* __restrict__ xl,
          const unsigned char* __restrict__ Wh,
          const unsigned char* __restrict__ Wl,
          __half* __restrict__ hout) {
    extern __shared__ __align__(16) unsigned char sm[];
    constexpr int XS     = 136;                    // bf16 row stride (elems)
    constexpr int XBUF   = 128 * XS * 2;           // 34816 (one hi or lo buf)
    constexpr int XPAIR  = 2 * XBUF;               // hi+lo for one stage
    constexpr int W_OFF  = 2 * XPAIR;              // 139264
    constexpr int WBYTES = NTILE * XS * 2;
    constexpr int WL_OFF = W_OFF + WBYTES;
    constexpr int NWTILE = NTILE / 4;              // warp n-tile (32 or 16)
    constexpr int NFRAG  = NWTILE / 8;             // n8 frags (4 or 2)
    constexpr int NF2    = NFRAG / 2;              // LDSM.x4 count (2 or 1)

    const int tid  = threadIdx.x;
    const int wid  = tid >> 5;
    const int lane = tid & 31;

    const uint32_t smb = smem_to_u32(sm);

    // prefetch lane mapping: 4 threads/row; each does 64B of hi + 64B of lo
    const int pr = tid >> 2;               // row 0..127
    const int ph = tid & 3;                // 32-elem quarter
    const uint32_t prel = (uint32_t)((pr * XS + ph * 32) * 2);  // byte off in buf

    // ---- prefetch one X tile (hi+lo) into smem buffer `buf` ----
    auto prefetch = [&](int t, int buf) {
        const uint32_t base = smb + buf * XPAIR;
        int gr = t * 128 + pr;
        if (gr < NN) {
            const __nv_bfloat16* sh_ = &xh[(size_t)gr * 128 + ph * 32];
            const __nv_bfloat16* sl_ = &xl[(size_t)gr * 128 + ph * 32];
            #pragma unroll
            for (int i = 0; i < 4; i++) {
                CP_ASYNC16(base + prel + i * 16, sh_ + i * 8);
                CP_ASYNC16(base + XBUF + prel + i * 16, sl_ + i * 8);
            }
        } else {
            uint4 z = make_uint4(0, 0, 0, 0);
            #pragma unroll
            for (int i = 0; i < 4; i++) {
                *(uint4*)(sm + buf * XPAIR + prel + i * 16) = z;
                *(uint4*)(sm + buf * XPAIR + XBUF + prel + i * 16) = z;
            }
        }
    };

    // ---- issue prefetch for first tile into buf 0 ----
    prefetch(blockIdx.x, 0);
    CP_COMMIT();

    // ---- W: copy once (overlaps with in-flight cp.async) ----
    {
        const float4* s4h = (const float4*)Wh;
        const float4* s4l = (const float4*)Wl;
        float4* d4h = (float4*)(sm + W_OFF);
        float4* d4l = (float4*)(sm + WL_OFF);
        for (int i = tid; i < WBYTES / 16; i += 512) {
            d4h[i] = s4h[i];
            d4l[i] = s4l[i];
        }
    }

    // per-lane ldmatrix offsets (relative to X buffer base / W base)
    const int m0 = (wid & 3) * 32;
    const int n0 = (wid >> 2) * NWTILE;
    const uint32_t aRel =
        (uint32_t)(((m0 + (lane & 15)) * XS + (lane >> 4) * 8) * 2);
    const uint32_t bH0 = smb + W_OFF +
        (uint32_t)(((n0 + (lane >> 4) * 8 + (lane & 7)) * XS + ((lane >> 3) & 1) * 8) * 2);

    const int g  = lane >> 2;
    const int tq = lane & 3;

    int buf = 0;
    for (int t = blockIdx.x; t < NTILES; t += gridDim.x, buf ^= 1) {
        const int row0 = t * 128;

        CP_WAIT0();
        __syncthreads();    // buf ready; all warps done reading buf (prev use)

        // ---- prefetch next tile into the other buffer (overlaps mainloop) ----
        {
            int tn = t + gridDim.x;
            if (tn < NTILES) prefetch(tn, buf ^ 1);
            CP_COMMIT();
        }

        // ---- mainloop: 8 k-steps, fragment double-buffer, term-major ----
        float acc[2][NFRAG][4];
        #pragma unroll
        for (int mi = 0; mi < 2; mi++)
            #pragma unroll
            for (int f = 0; f < NFRAG; f++)
                #pragma unroll
                for (int q = 0; q < 4; q++) acc[mi][f][q] = 0.f;

        uint32_t AHf[2][2][4], ALf[2][2][4];
        uint32_t BHf[2][NF2][4], BLf[2][NF2][4];

        uint32_t aH = smb + buf * XPAIR + aRel;
        uint32_t aL = aH + XBUF;
        uint32_t bH = bH0, bL = bH0 + WBYTES;
        LDSM4(AHf[0][0], aH);
        LDSM4(AHf[0][1], aH + 16 * XS * 2);
        LDSM4(ALf[0][0], aL);
        LDSM4(ALf[0][1], aL + 16 * XS * 2);
        #pragma unroll
        for (int j = 0; j < NF2; j++) {
            LDSM4(BHf[0][j], bH + j * 16 * XS * 2);
            LDSM4(BLf[0][j], bL + j * 16 * XS * 2);
        }

        #pragma unroll
        for (int ks = 0; ks < 8; ks++) {
            const int cur = ks & 1;
            const int nxt = cur ^ 1;
            if (ks < 7) {
                aH += 32; aL += 32; bH += 32; bL += 32;
                LDSM4(AHf[nxt][0], aH);
                LDSM4(AHf[nxt][1], aH + 16 * XS * 2);
                LDSM4(ALf[nxt][0], aL);
                LDSM4(ALf[nxt][1], aL + 16 * XS * 2);
                #pragma unroll
                for (int j = 0; j < NF2; j++) {
                    LDSM4(BHf[nxt][j], bH + j * 16 * XS * 2);
                    LDSM4(BLf[nxt][j], bL + j * 16 * XS * 2);
                }
            }
            // term 0: AH x BH
            #pragma unroll
            for (int mi = 0; mi < 2; mi++)
                #pragma unroll
                for (int j = 0; j < NF2; j++)
                    #pragma unroll
                    for (int h = 0; h < 2; h++)
                        MMA_BF16(acc[mi][j * 2 + h], AHf[cur][mi],
                                 BHf[cur][j][h * 2], BHf[cur][j][h * 2 + 1]);
            // term 1: AL x BH
            #pragma unroll
            for (int mi = 0; mi < 2; mi++)
                #pragma unroll
                for (int j = 0; j < NF2; j++)
                    #pragma unroll
                    for (int h = 0; h < 2; h++)
                        MMA_BF16(acc[mi][j * 2 + h], ALf[cur][mi],
                                 BHf[cur][j][h * 2], BHf[cur][j][h * 2 + 1]);
            // term 2: AH x BL
            #pragma unroll
            for (int mi = 0; mi < 2; mi++)
                #pragma unroll
                for (int j = 0; j < NF2; j++)
                    #pragma unroll
                    for (int h = 0; h < 2; h++)
                        MMA_BF16(acc[mi][j * 2 + h], AHf[cur][mi],
                                 BLf[cur][j][h * 2], BLf[cur][j][h * 2 + 1]);
        }

        // ---- epilogue: scale by norm_out, store fp16 ----
        #pragma unroll
        for (int mi = 0; mi < 2; mi++) {
            int r1 = row0 + m0 + mi * 16 + g;
            int r2 = r1 + 8;
            float s1 = (r1 < NN) ? g_norm_out[r1] : 0.f;
            float s2 = (r2 < NN) ? g_norm_out[r2] : 0.f;
            #pragma unroll
            for (int f = 0; f < NFRAG; f++) {
                int n = n0 + f * 8 + tq * 2;
                if (OUTC < NTILE && n >= OUTC) continue;
                float* c = acc[mi][f];
                if (r1 < NN) {
                    __half2 hv = __floats2half2_rn(c[0] * s1, c[1] * s1);
                    *(__half2*)&hout[(size_t)r1 * OUTC + n] = hv;
                }
                if (r2 < NN) {
                    __half2 hv = __floats2half2_rn(c[2] * s2, c[3] * s2);
                    *(__half2*)&hout[(size_t)r2 * OUTC + n] = hv;
                }
            }
        }
    }
}

// ===========================================================================
// Aggregation 128-dim: one warp per dst node; CSR gather (fp16), fp32 accum.
// Writes bf16 hi/lo activation buffers (GEMM input format).
// ===========================================================================
__global__ void __launch_bounds__(256)
agg128(const float* __restrict__ bias) {
    int w = (blockIdx.x * blockDim.x + threadIdx.x) >> 5;
    if (w >= NN) return;
    int lane = threadIdx.x & 31;
    int beg = g_offs[w], end = g_offs[w + 1];

    float4 acc = make_float4(0.f, 0.f, 0.f, 0.f);
    int e = beg;
    for (; e + 4 <= end; e += 4) {
        int s0 = g_csr[e],     s1 = g_csr[e + 1];
        int s2 = g_csr[e + 2], s3 = g_csr[e + 3];
        uint2 u0 = *(const uint2*)&g_hbuf[(size_t)s0 * 128 + lane * 4];
        uint2 u1 = *(const uint2*)&g_hbuf[(size_t)s1 * 128 + lane * 4];
        uint2 u2 = *(const uint2*)&g_hbuf[(size_t)s2 * 128 + lane * 4];
        uint2 u3 = *(const uint2*)&g_hbuf[(size_t)s3 * 128 + lane * 4];
        float2 a0 = __half22float2(*(__half2*)&u0.x), b0 = __half22float2(*(__half2*)&u0.y);
        float2 a1 = __half22float2(*(__half2*)&u1.x), b1 = __half22float2(*(__half2*)&u1.y);
        float2 a2 = __half22float2(*(__half2*)&u2.x), b2 = __half22float2(*(__half2*)&u2.y);
        float2 a3 = __half22float2(*(__half2*)&u3.x), b3 = __half22float2(*(__half2*)&u3.y);
        acc.x += (a0.x + a1.x) + (a2.x + a3.x);
        acc.y += (a0.y + a1.y) + (a2.y + a3.y);
        acc.z += (b0.x + b1.x) + (b2.x + b3.x);
        acc.w += (b0.y + b1.y) + (b2.y + b3.y);
    }
    for (; e < end; e++) {
        int s0 = g_csr[e];
        uint2 u0 = *(const uint2*)&g_hbuf[(size_t)s0 * 128 + lane * 4];
        float2 a0 = __half22float2(*(__half2*)&u0.x), b0 = __half22float2(*(__half2*)&u0.y);
        acc.x += a0.x; acc.y += a0.y; acc.z += b0.x; acc.w += b0.y;
    }

    float sc = g_norm_in[w];
    float4 b = *(const float4*)&bias[lane * 4];
    float4 o;
    o.x = fmaxf(fmaf(acc.x, sc, b.x), 0.f);
    o.y = fmaxf(fmaf(acc.y, sc, b.y), 0.f);
    o.z = fmaxf(fmaf(acc.z, sc, b.z), 0.f);
    o.w = fmaxf(fmaf(acc.w, sc, b.w), 0.f);

    __nv_bfloat16 h0, h1, h2, h3, l0, l1, l2, l3;
    bf16_split(o.x, h0, l0); bf16_split(o.y, h1, l1);
    bf16_split(o.z, h2, l2); bf16_split(o.w, h3, l3);
    __nv_bfloat162 hp0(h0, h1), hp1(h2, h3), lp0(l0, l1), lp1(l2, l3);
    uint2 hv = make_uint2(*(uint32_t*)&hp0, *(uint32_t*)&hp1);
    uint2 lv = make_uint2(*(uint32_t*)&lp0, *(uint32_t*)&lp1);
    *(uint2*)&g_xh[(size_t)w * 128 + lane * 4] = hv;
    *(uint2*)&g_xl[(size_t)w * 128 + lane * 4] = lv;
}

// ===========================================================================
// Aggregation 40-dim (final layer, no relu) -> d_out (fp32)
// ===========================================================================
__global__ void __launch_bounds__(256)
agg40(const float* __restrict__ bias, float* __restrict__ out) {
    int w = (blockIdx.x * blockDim.x + threadIdx.x) >> 5;
    if (w >= NN) return;
    int lane = threadIdx.x & 31;
    int beg = g_offs[w], end = g_offs[w + 1];
    if (lane >= 20) return;

    float2 acc = make_float2(0.f, 0.f);
    int e = beg;
    for (; e + 2 <= end; e += 2) {
        int s0 = g_csr[e], s1 = g_csr[e + 1];
        __half2 h0 = *(const __half2*)&g_hbuf[(size_t)s0 * 40 + lane * 2];
        __half2 h1 = *(const __half2*)&g_hbuf[(size_t)s1 * 40 + lane * 2];
        float2 f0 = __half22float2(h0);
        float2 f1 = __half22float2(h1);
        acc.x += f0.x + f1.x;
        acc.y += f0.y + f1.y;
    }
    if (e < end) {
        int s0 = g_csr[e];
        float2 f0 = __half22float2(*(const __half2*)&g_hbuf[(size_t)s0 * 40 + lane * 2]);
        acc.x += f0.x; acc.y += f0.y;
    }
    float sc = g_norm_in[w];
    float2 o;
    o.x = fmaf(acc.x, sc, bias[lane * 2]);
    o.y = fmaf(acc.y, sc, bias[lane * 2 + 1]);
    *(float2*)&out[(size_t)w * 40 + lane * 2] = o;
}

// ===========================================================================
extern "C" void kernel_launch(void* const* d_in, const int* in_sizes, int n_in,
                              void* d_out, int out_size) {
    const float* feat = (const float*)d_in[0];
    const int*   src  = (const int*)  d_in[1];
    const int*   dst  = (const int*)  d_in[2];
    const float* W0   = (const float*)d_in[3];
    const float* b0   = (const float*)d_in[4];
    const float* W1   = (const float*)d_in[5];
    const float* b1   = (const float*)d_in[6];
    const float* W2   = (const float*)d_in[7];
    const float* b2   = (const float*)d_in[8];
    float* out = (float*)d_out;

    const int NB = (NN + 255) / 256;
    const int EB = (EE + 255) / 256;
    const int SB = (NN + 1023) / 1024;
    const int AGGB = (NN * 32 + 255) / 256;
    const int FB = (NN * 32 + 255) / 256;

    // smem: X double-buffer (hi+lo)x2 = 139264 ; W(hi+lo) = 2*NTILE*136*2
    const int SMEM_BIG   = 4 * 128 * 136 * 2 + 2 * 128 * 136 * 2;  // 208896
    const int SMEM_SMALL = 4 * 128 * 136 * 2 + 2 * 64 * 136 * 2;   // 174080

    static cudaStream_t s2 = nullptr;
    static cudaEvent_t evF = nullptr, evJ = nullptr;
    static bool init_done = false;
    if (!init_done) {
        cudaFuncSetAttribute(gemm_pers<128, 128>,
                             cudaFuncAttributeMaxDynamicSharedMemorySize, SMEM_BIG);
        cudaFuncSetAttribute(gemm_pers<64, 40>,
                             cudaFuncAttributeMaxDynamicSharedMemorySize, SMEM_SMALL);
        cudaStreamCreateWithFlags(&s2, cudaStreamNonBlocking);
        cudaEventCreateWithFlags(&evF, cudaEventDisableTiming);
        cudaEventCreateWithFlags(&evJ, cudaEventDisableTiming);
        init_done = true;
    }

    unsigned char *p_B0h, *p_B0l, *p_B1h, *p_B1l, *p_B2h, *p_B2l;
    cudaGetSymbolAddress((void**)&p_B0h, g_B0h);
    cudaGetSymbolAddress((void**)&p_B0l, g_B0l);
    cudaGetSymbolAddress((void**)&p_B1h, g_B1h);
    cudaGetSymbolAddress((void**)&p_B1l, g_B1l);
    cudaGetSymbolAddress((void**)&p_B2h, g_B2h);
    cudaGetSymbolAddress((void**)&p_B2l, g_B2l);
    __half* p_hbuf;
    __nv_bfloat16 *p_xh, *p_xl;
    cudaGetSymbolAddress((void**)&p_hbuf, g_hbuf);
    cudaGetSymbolAddress((void**)&p_xh, g_xh);
    cudaGetSymbolAddress((void**)&p_xl, g_xl);

    // common prep
    k_zero<<<NB, 256>>>();
    k_deg<<<EB, 256>>>(src, dst);
    k_norm_wtiles<<<NB, 256>>>(W0, W1, W2);

    // fork: feat-convert + layer-0 GEMM on s2, CSR build on main stream
    cudaEventRecord(evF, 0);
    cudaStreamWaitEvent(s2, evF, 0);
    k_feat<<<FB, 256, 0, s2>>>(feat);
    gemm_pers<128, 128><<<PGRID, 512, SMEM_BIG, s2>>>(p_xh, p_xl, p_B0h, p_B0l, p_hbuf);
    k_scan1<<<SB, 1024>>>();
    k_scan2<<<1, 128>>>(SB);
    k_scan3<<<NB, 256>>>();
    k_scatter<<<EB, 256>>>(src, dst);
    cudaEventRecord(evJ, s2);
    cudaStreamWaitEvent(0, evJ, 0);

    // layer 0 aggregation (writes g_xh/g_xl for next GEMM)
    agg128<<<AGGB, 256>>>(b0);
    // layer 1
    gemm_pers<128, 128><<<PGRID, 512, SMEM_BIG>>>(p_xh, p_xl, p_B1h, p_B1l, p_hbuf);
    agg128<<<AGGB, 256>>>(b1);
    // layer 2
    gemm_pers<64, 40><<<PGRID, 512, SMEM_SMALL>>>(p_xh, p_xl, p_B2h, p_B2l, p_hbuf);
    agg40<<<AGGB, 256>>>(b2, out);
}

// round 12
// speedup vs baseline: 1.1456x; 1.0868x over previous
#include <cuda_runtime.h>
#include <cuda_bf16.h>
#include <cuda_fp16.h>
#include <math.h>
#include <stdint.h>

#define NN 100000
#define EE 1600000
#define HD 128
#define CD 40
#define NTILES 782            // ceil(NN/128)
#define PGRID 148             // persistent grid (1 CTA/SM)

// -------- scratch (static __device__ arrays; allocation forbidden) --------
__device__ __half g_hbuf[(size_t)NN * HD];  // GEMM out (gather src)
__device__ __half g_xh[(size_t)NN * HD];    // activation hi fp16 (GEMM in)
__device__ __half g_xl[(size_t)NN * HD];    // activation lo fp16 (GEMM in)
__device__ int    g_deg_out[NN];
__device__ int    g_deg_in[NN];
__device__ float  g_norm_out[NN];
__device__ float  g_norm_in[NN];
__device__ int    g_offs[NN + 1];
__device__ int    g_cursor[NN];
__device__ int    g_bsums[128];
__device__ int    g_csr[EE];

// Pre-built W operand tiles: [n][k] fp16, padded row stride 136 elems.
__device__ __align__(16) unsigned char g_B0h[128 * 136 * 2];
__device__ __align__(16) unsigned char g_B1h[128 * 136 * 2];
__device__ __align__(16) unsigned char g_B2h[64 * 136 * 2];

// ===========================================================================
// helpers (baseline sm_80 features -- no 'a'-gated PTX)
// ===========================================================================
__device__ __forceinline__ uint32_t smem_to_u32(const void* p) {
    uint32_t a;
    asm("{ .reg .u64 t; cvta.to.shared.u64 t, %1; cvt.u32.u64 %0, t; }"
        : "=r"(a) : "l"(p));
    return a;
}

#define LDSM4(r, addr) \
    asm volatile("ldmatrix.sync.aligned.m8n8.x4.shared.b16 {%0,%1,%2,%3}, [%4];" \
        : "=r"((r)[0]), "=r"((r)[1]), "=r"((r)[2]), "=r"((r)[3]) : "r"(addr))

#define MMA_F16(d, a, b0, b1) \
    asm volatile("mma.sync.aligned.m16n8k16.row.col.f32.f16.f16.f32 " \
        "{%0,%1,%2,%3}, {%4,%5,%6,%7}, {%8,%9}, {%0,%1,%2,%3};" \
        : "+f"((d)[0]), "+f"((d)[1]), "+f"((d)[2]), "+f"((d)[3]) \
        : "r"((a)[0]), "r"((a)[1]), "r"((a)[2]), "r"((a)[3]), "r"(b0), "r"(b1))

#define CP_ASYNC16(dst_u32, src_ptr) \
    asm volatile("cp.async.cg.shared.global [%0], [%1], 16;" \
        :: "r"(dst_u32), "l"(src_ptr) : "memory")
#define CP_COMMIT() asm volatile("cp.async.commit_group;" ::: "memory")
#define CP_WAIT0()  asm volatile("cp.async.wait_group 0;" ::: "memory")

// split a float into fp16 hi/lo (lo residual ~2^-22 -- effectively exact)
__device__ __forceinline__ void fp16_split(float v, __half& h, __half& l) {
    h = __float2half_rn(v);
    l = __float2half_rn(v - __half2float(h));
}

// ===========================================================================
// Degrees + norms + CSR build
// ===========================================================================
__global__ void k_zero() {
    int i = blockIdx.x * blockDim.x + threadIdx.x;
    if (i < NN) { g_deg_out[i] = 0; g_deg_in[i] = 0; g_cursor[i] = 0; }
}

__global__ void k_deg(const int* __restrict__ src, const int* __restrict__ dst) {
    int e = blockIdx.x * blockDim.x + threadIdx.x;
    if (e < EE) {
        atomicAdd(&g_deg_out[src[e]], 1);
        atomicAdd(&g_deg_in[dst[e]], 1);
    }
}

// Fused: per-node norms + W-tile build ([n][k] fp16, stride 136)
__global__ void k_norm_wtiles(const float* __restrict__ W0,
                              const float* __restrict__ W1,
                              const float* __restrict__ W2) {
    int i = blockIdx.x * blockDim.x + threadIdx.x;
    if (i < NN) {
        int d0 = g_deg_out[i];
        int d1 = g_deg_in[i];
        g_norm_out[i] = d0 > 0 ? rsqrtf((float)d0) : 0.f;
        g_norm_in[i]  = d1 > 0 ? rsqrtf((float)d1) : 0.f;
    }
    if (i < 40960) {
        float val;
        unsigned char *ph;
        int n, k;
        if (i < 32768) {
            const float* W = (i < 16384) ? W0 : W1;
            ph = (i < 16384) ? g_B0h : g_B1h;
            int e = i & 16383;
            n = e >> 7; k = e & 127;
            val = W[k * 128 + n];
        } else {
            int e = i - 32768;
            n = e >> 7; k = e & 127;      // n in [0,64)
            val = (n < CD) ? W2[k * CD + n] : 0.f;
            ph = g_B2h;
        }
        uint32_t off = ((uint32_t)n * 136u + (uint32_t)k) * 2u;
        *(__half*)(ph + off) = __float2half_rn(val);
    }
}

// Convert input features fp32 -> fp16 hi/lo buffers (one float4 per thread)
__global__ void k_feat(const float* __restrict__ feat) {
    size_t i = (size_t)blockIdx.x * blockDim.x + threadIdx.x;
    if (i >= (size_t)NN * 32) return;
    float4 v = ((const float4*)feat)[i];
    __half h0, h1, h2, h3, l0, l1, l2, l3;
    fp16_split(v.x, h0, l0); fp16_split(v.y, h1, l1);
    fp16_split(v.z, h2, l2); fp16_split(v.w, h3, l3);
    __half2 hp0(h0, h1), hp1(h2, h3), lp0(l0, l1), lp1(l2, l3);
    uint2 hv = make_uint2(*(uint32_t*)&hp0, *(uint32_t*)&hp1);
    uint2 lv = make_uint2(*(uint32_t*)&lp0, *(uint32_t*)&lp1);
    ((uint2*)g_xh)[i] = hv;
    ((uint2*)g_xl)[i] = lv;
}

__global__ void k_scan1() {
    __shared__ int sh[1024];
    int i = blockIdx.x * 1024 + threadIdx.x;
    int v = (i < NN) ? g_deg_in[i] : 0;
    sh[threadIdx.x] = v;
    __syncthreads();
    #pragma unroll
    for (int d = 1; d < 1024; d <<= 1) {
        int t = 0;
        if ((int)threadIdx.x >= d) t = sh[threadIdx.x - d];
        __syncthreads();
        sh[threadIdx.x] += t;
        __syncthreads();
    }
    if (i < NN) g_offs[i + 1] = sh[threadIdx.x];
    if (threadIdx.x == 1023) g_bsums[blockIdx.x] = sh[1023];
}

__global__ void k_scan2(int nb) {
    __shared__ int sh[128];
    int t = threadIdx.x;
    int v = (t < nb) ? g_bsums[t] : 0;
    sh[t] = v;
    __syncthreads();
    #pragma unroll
    for (int d = 1; d < 128; d <<= 1) {
        int x = 0;
        if (t >= d) x = sh[t - d];
        __syncthreads();
        sh[t] += x;
        __syncthreads();
    }
    if (t < nb) g_bsums[t] = sh[t] - v;   // exclusive
}

__global__ void k_scan3() {
    int i = blockIdx.x * blockDim.x + threadIdx.x;
    if (i == 0) g_offs[0] = 0;
    if (i < NN) g_offs[i + 1] += g_bsums[i >> 10];
}

__global__ void k_scatter(const int* __restrict__ src, const int* __restrict__ dst) {
    int e = blockIdx.x * blockDim.x + threadIdx.x;
    if (e < EE) {
        int d = dst[e];
        int pos = g_offs[d] + atomicAdd(&g_cursor[d], 1);
        g_csr[pos] = src[e];
    }
}

// ===========================================================================
// Persistent HMMA GEMM: hout[r,0:OUTC] = fp16(norm_out[r] * (x[r,:] @ W))
// 2-TERM fp16 emulation: D = Ah*B + Al*B  (A fp16 hi/lo, W plain fp16).
// X in fp16 hi/lo in global -> cp.async into double-buffered smem.
// 512 thr, one barrier per tile, term-major order.
// ===========================================================================
template <int NTILE, int OUTC>
__global__ void __launch_bounds__(512)
gemm_pers(const __half* __restrict__ xh,
          const __half* __restrict__ xl,
          const unsigned char* __restrict__ Wh,
          __half* __restrict__ hout) {
    extern __shared__ __align__(16) unsigned char sm[];
    constexpr int XS     = 136;                    // fp16 row stride (elems)
    constexpr int XBUF   = 128 * XS * 2;           // 34816 (one hi or lo buf)
    constexpr int XPAIR  = 2 * XBUF;               // hi+lo for one stage
    constexpr int W_OFF  = 2 * XPAIR;              // 139264
    constexpr int WBYTES = NTILE * XS * 2;
    constexpr int NWTILE = NTILE / 4;              // warp n-tile (32 or 16)
    constexpr int NFRAG  = NWTILE / 8;             // n8 frags (4 or 2)
    constexpr int NF2    = NFRAG / 2;              // LDSM.x4 count (2 or 1)

    const int tid  = threadIdx.x;
    const int wid  = tid >> 5;
    const int lane = tid & 31;

    const uint32_t smb = smem_to_u32(sm);

    // prefetch lane mapping: 4 threads/row; each does 64B of hi + 64B of lo
    const int pr = tid >> 2;               // row 0..127
    const int ph = tid & 3;                // 32-elem quarter
    const uint32_t prel = (uint32_t)((pr * XS + ph * 32) * 2);  // byte off in buf

    auto prefetch = [&](int t, int buf) {
        const uint32_t base = smb + buf * XPAIR;
        int gr = t * 128 + pr;
        if (gr < NN) {
            const __half* sh_ = &xh[(size_t)gr * 128 + ph * 32];
            const __half* sl_ = &xl[(size_t)gr * 128 + ph * 32];
            #pragma unroll
            for (int i = 0; i < 4; i++) {
                CP_ASYNC16(base + prel + i * 16, sh_ + i * 8);
                CP_ASYNC16(base + XBUF + prel + i * 16, sl_ + i * 8);
            }
        } else {
            uint4 z = make_uint4(0, 0, 0, 0);
            #pragma unroll
            for (int i = 0; i < 4; i++) {
                *(uint4*)(sm + buf * XPAIR + prel + i * 16) = z;
                *(uint4*)(sm + buf * XPAIR + XBUF + prel + i * 16) = z;
            }
        }
    };

    prefetch(blockIdx.x, 0);
    CP_COMMIT();

    // ---- W: copy once ----
    {
        const float4* s4h = (const float4*)Wh;
        float4* d4h = (float4*)(sm + W_OFF);
        for (int i = tid; i < WBYTES / 16; i += 512) d4h[i] = s4h[i];
    }

    const int m0 = (wid & 3) * 32;
    const int n0 = (wid >> 2) * NWTILE;
    const uint32_t aRel =
        (uint32_t)(((m0 + (lane & 15)) * XS + (lane >> 4) * 8) * 2);
    const uint32_t bH0 = smb + W_OFF +
        (uint32_t)(((n0 + (lane >> 4) * 8 + (lane & 7)) * XS + ((lane >> 3) & 1) * 8) * 2);

    const int g  = lane >> 2;
    const int tq = lane & 3;

    int buf = 0;
    for (int t = blockIdx.x; t < NTILES; t += gridDim.x, buf ^= 1) {
        const int row0 = t * 128;

        CP_WAIT0();
        __syncthreads();    // buf ready; all warps done reading prev buf

        // ---- prefetch next tile into the other buffer (overlaps mainloop) ----
        {
            int tn = t + gridDim.x;
            if (tn < NTILES) prefetch(tn, buf ^ 1);
            CP_COMMIT();
        }

        // ---- mainloop: 8 k-steps, fragment double-buffer, term-major ----
        float acc[2][NFRAG][4];
        #pragma unroll
        for (int mi = 0; mi < 2; mi++)
            #pragma unroll
            for (int f = 0; f < NFRAG; f++)
                #pragma unroll
                for (int q = 0; q < 4; q++) acc[mi][f][q] = 0.f;

        uint32_t AHf[2][2][4], ALf[2][2][4];
        uint32_t BHf[2][NF2][4];

        uint32_t aH = smb + buf * XPAIR + aRel;
        uint32_t aL = aH + XBUF;
        uint32_t bH = bH0;
        LDSM4(AHf[0][0], aH);
        LDSM4(AHf[0][1], aH + 16 * XS * 2);
        LDSM4(ALf[0][0], aL);
        LDSM4(ALf[0][1], aL + 16 * XS * 2);
        #pragma unroll
        for (int j = 0; j < NF2; j++)
            LDSM4(BHf[0][j], bH + j * 16 * XS * 2);

        #pragma unroll
        for (int ks = 0; ks < 8; ks++) {
            const int cur = ks & 1;
            const int nxt = cur ^ 1;
            if (ks < 7) {
                aH += 32; aL += 32; bH += 32;
                LDSM4(AHf[nxt][0], aH);
                LDSM4(AHf[nxt][1], aH + 16 * XS * 2);
                LDSM4(ALf[nxt][0], aL);
                LDSM4(ALf[nxt][1], aL + 16 * XS * 2);
                #pragma unroll
                for (int j = 0; j < NF2; j++)
                    LDSM4(BHf[nxt][j], bH + j * 16 * XS * 2);
            }
            // term 0: AH x B
            #pragma unroll
            for (int mi = 0; mi < 2; mi++)
                #pragma unroll
                for (int j = 0; j < NF2; j++)
                    #pragma unroll
                    for (int h = 0; h < 2; h++)
                        MMA_F16(acc[mi][j * 2 + h], AHf[cur][mi],
                                BHf[cur][j][h * 2], BHf[cur][j][h * 2 + 1]);
            // term 1: AL x B
            #pragma unroll
            for (int mi = 0; mi < 2; mi++)
                #pragma unroll
                for (int j = 0; j < NF2; j++)
                    #pragma unroll
                    for (int h = 0; h < 2; h++)
                        MMA_F16(acc[mi][j * 2 + h], ALf[cur][mi],
                                BHf[cur][j][h * 2], BHf[cur][j][h * 2 + 1]);
        }

        // ---- epilogue: scale by norm_out, store fp16 ----
        #pragma unroll
        for (int mi = 0; mi < 2; mi++) {
            int r1 = row0 + m0 + mi * 16 + g;
            int r2 = r1 + 8;
            float s1 = (r1 < NN) ? g_norm_out[r1] : 0.f;
            float s2 = (r2 < NN) ? g_norm_out[r2] : 0.f;
            #pragma unroll
            for (int f = 0; f < NFRAG; f++) {
                int n = n0 + f * 8 + tq * 2;
                if (OUTC < NTILE && n >= OUTC) continue;
                float* c = acc[mi][f];
                if (r1 < NN) {
                    __half2 hv = __floats2half2_rn(c[0] * s1, c[1] * s1);
                    *(__half2*)&hout[(size_t)r1 * OUTC + n] = hv;
                }
                if (r2 < NN) {
                    __half2 hv = __floats2half2_rn(c[2] * s2, c[3] * s2);
                    *(__half2*)&hout[(size_t)r2 * OUTC + n] = hv;
                }
            }
        }
    }
}

// ===========================================================================
// Aggregation 128-dim: one warp per dst node; CSR gather (fp16), fp32 accum.
// Writes fp16 hi/lo activation buffers (GEMM input format).
// ===========================================================================
__global__ void __launch_bounds__(256)
agg128(const float* __restrict__ bias) {
    int w = (blockIdx.x * blockDim.x + threadIdx.x) >> 5;
    if (w >= NN) return;
    int lane = threadIdx.x & 31;
    int beg = g_offs[w], end = g_offs[w + 1];

    float4 acc = make_float4(0.f, 0.f, 0.f, 0.f);
    int e = beg;
    for (; e + 4 <= end; e += 4) {
        int s0 = g_csr[e],     s1 = g_csr[e + 1];
        int s2 = g_csr[e + 2], s3 = g_csr[e + 3];
        uint2 u0 = *(const uint2*)&g_hbuf[(size_t)s0 * 128 + lane * 4];
        uint2 u1 = *(const uint2*)&g_hbuf[(size_t)s1 * 128 + lane * 4];
        uint2 u2 = *(const uint2*)&g_hbuf[(size_t)s2 * 128 + lane * 4];
        uint2 u3 = *(const uint2*)&g_hbuf[(size_t)s3 * 128 + lane * 4];
        float2 a0 = __half22float2(*(__half2*)&u0.x), b0 = __half22float2(*(__half2*)&u0.y);
        float2 a1 = __half22float2(*(__half2*)&u1.x), b1 = __half22float2(*(__half2*)&u1.y);
        float2 a2 = __half22float2(*(__half2*)&u2.x), b2 = __half22float2(*(__half2*)&u2.y);
        float2 a3 = __half22float2(*(__half2*)&u3.x), b3 = __half22float2(*(__half2*)&u3.y);
        acc.x += (a0.x + a1.x) + (a2.x + a3.x);
        acc.y += (a0.y + a1.y) + (a2.y + a3.y);
        acc.z += (b0.x + b1.x) + (b2.x + b3.x);
        acc.w += (b0.y + b1.y) + (b2.y + b3.y);
    }
    for (; e < end; e++) {
        int s0 = g_csr[e];
        uint2 u0 = *(const uint2*)&g_hbuf[(size_t)s0 * 128 + lane * 4];
        float2 a0 = __half22float2(*(__half2*)&u0.x), b0 = __half22float2(*(__half2*)&u0.y);
        acc.x += a0.x; acc.y += a0.y; acc.z += b0.x; acc.w += b0.y;
    }

    float sc = g_norm_in[w];
    float4 b = *(const float4*)&bias[lane * 4];
    float4 o;
    o.x = fmaxf(fmaf(acc.x, sc, b.x), 0.f);
    o.y = fmaxf(fmaf(acc.y, sc, b.y), 0.f);
    o.z = fmaxf(fmaf(acc.z, sc, b.z), 0.f);
    o.w = fmaxf(fmaf(acc.w, sc, b.w), 0.f);

    __half h0, h1, h2, h3, l0, l1, l2, l3;
    fp16_split(o.x, h0, l0); fp16_split(o.y, h1, l1);
    fp16_split(o.z, h2, l2); fp16_split(o.w, h3, l3);
    __half2 hp0(h0, h1), hp1(h2, h3), lp0(l0, l1), lp1(l2, l3);
    uint2 hv = make_uint2(*(uint32_t*)&hp0, *(uint32_t*)&hp1);
    uint2 lv = make_uint2(*(uint32_t*)&lp0, *(uint32_t*)&lp1);
    *(uint2*)&g_xh[(size_t)w * 128 + lane * 4] = hv;
    *(uint2*)&g_xl[(size_t)w * 128 + lane * 4] = lv;
}

// ===========================================================================
// Aggregation 40-dim (final layer, no relu) -> d_out (fp32)
// ===========================================================================
__global__ void __launch_bounds__(256)
agg40(const float* __restrict__ bias, float* __restrict__ out) {
    int w = (blockIdx.x * blockDim.x + threadIdx.x) >> 5;
    if (w >= NN) return;
    int lane = threadIdx.x & 31;
    int beg = g_offs[w], end = g_offs[w + 1];
    if (lane >= 20) return;

    float2 acc = make_float2(0.f, 0.f);
    int e = beg;
    for (; e + 2 <= end; e += 2) {
        int s0 = g_csr[e], s1 = g_csr[e + 1];
        __half2 h0 = *(const __half2*)&g_hbuf[(size_t)s0 * 40 + lane * 2];
        __half2 h1 = *(const __half2*)&g_hbuf[(size_t)s1 * 40 + lane * 2];
        float2 f0 = __half22float2(h0);
        float2 f1 = __half22float2(h1);
        acc.x += f0.x + f1.x;
        acc.y += f0.y + f1.y;
    }
    if (e < end) {
        int s0 = g_csr[e];
        float2 f0 = __half22float2(*(const __half2*)&g_hbuf[(size_t)s0 * 40 + lane * 2]);
        acc.x += f0.x; acc.y += f0.y;
    }
    float sc = g_norm_in[w];
    float2 o;
    o.x = fmaf(acc.x, sc, bias[lane * 2]);
    o.y = fmaf(acc.y, sc, bias[lane * 2 + 1]);
    *(float2*)&out[(size_t)w * 40 + lane * 2] = o;
}

// ===========================================================================
extern "C" void kernel_launch(void* const* d_in, const int* in_sizes, int n_in,
                              void* d_out, int out_size) {
    const float* feat = (const float*)d_in[0];
    const int*   src  = (const int*)  d_in[1];
    const int*   dst  = (const int*)  d_in[2];
    const float* W0   = (const float*)d_in[3];
    const float* b0   = (const float*)d_in[4];
    const float* W1   = (const float*)d_in[5];
    const float* b1   = (const float*)d_in[6];
    const float* W2   = (const float*)d_in[7];
    const float* b2   = (const float*)d_in[8];
    float* out = (float*)d_out;

    const int NB = (NN + 255) / 256;
    const int EB = (EE + 255) / 256;
    const int SB = (NN + 1023) / 1024;
    const int AGGB = (NN * 32 + 255) / 256;
    const int FB = (NN * 32 + 255) / 256;

    // smem: X double-buffer (hi+lo)x2 = 139264 ; W = NTILE*136*2
    const int SMEM_BIG   = 4 * 128 * 136 * 2 + 128 * 136 * 2;  // 174080
    const int SMEM_SMALL = 4 * 128 * 136 * 2 + 64 * 136 * 2;   // 156672

    static cudaStream_t s2 = nullptr;
    static cudaEvent_t evF = nullptr, evJ = nullptr;
    static bool init_done = false;
    if (!init_done) {
        cudaFuncSetAttribute(gemm_pers<128, 128>,
                             cudaFuncAttributeMaxDynamicSharedMemorySize, SMEM_BIG);
        cudaFuncSetAttribute(gemm_pers<64, 40>,
                             cudaFuncAttributeMaxDynamicSharedMemorySize, SMEM_SMALL);
        cudaStreamCreateWithFlags(&s2, cudaStreamNonBlocking);
        cudaEventCreateWithFlags(&evF, cudaEventDisableTiming);
        cudaEventCreateWithFlags(&evJ, cudaEventDisableTiming);
        init_done = true;
    }

    unsigned char *p_B0h, *p_B1h, *p_B2h;
    cudaGetSymbolAddress((void**)&p_B0h, g_B0h);
    cudaGetSymbolAddress((void**)&p_B1h, g_B1h);
    cudaGetSymbolAddress((void**)&p_B2h, g_B2h);
    __half* p_hbuf;
    __half *p_xh, *p_xl;
    cudaGetSymbolAddress((void**)&p_hbuf, g_hbuf);
    cudaGetSymbolAddress((void**)&p_xh, g_xh);
    cudaGetSymbolAddress((void**)&p_xl, g_xl);

    // common prep
    k_zero<<<NB, 256>>>();
    k_deg<<<EB, 256>>>(src, dst);
    k_norm_wtiles<<<NB, 256>>>(W0, W1, W2);

    // fork: feat-convert + layer-0 GEMM on s2, CSR build on main stream
    cudaEventRecord(evF, 0);
    cudaStreamWaitEvent(s2, evF, 0);
    k_feat<<<FB, 256, 0, s2>>>(feat);
    gemm_pers<128, 128><<<PGRID, 512, SMEM_BIG, s2>>>(p_xh, p_xl, p_B0h, p_hbuf);
    k_scan1<<<SB, 1024>>>();
    k_scan2<<<1, 128>>>(SB);
    k_scan3<<<NB, 256>>>();
    k_scatter<<<EB, 256>>>(src, dst);
    cudaEventRecord(evJ, s2);
    cudaStreamWaitEvent(0, evJ, 0);

    // layer 0 aggregation (writes g_xh/g_xl for next GEMM)
    agg128<<<AGGB, 256>>>(b0);
    // layer 1
    gemm_pers<128, 128><<<PGRID, 512, SMEM_BIG>>>(p_xh, p_xl, p_B1h, p_hbuf);
    agg128<<<AGGB, 256>>>(b1);
    // layer 2
    gemm_pers<64, 40><<<PGRID, 512, SMEM_SMALL>>>(p_xh, p_xl, p_B2h, p_hbuf);
    agg40<<<AGGB, 256>>>(b2, out);
}

// round 13
// speedup vs baseline: 1.2574x; 1.0975x over previous
#include <cuda_runtime.h>
#include <cuda_bf16.h>
#include <cuda_fp16.h>
#include <math.h>
#include <stdint.h>

#define NN 100000
#define EE 1600000
#define HD 128
#define CD 40
#define NTILES 782            // ceil(NN/128)
#define PGRID 148             // persistent grid (1 CTA/SM)

// -------- scratch (static __device__ arrays; allocation forbidden) --------
__device__ __half g_hbuf[(size_t)NN * HD];  // GEMM out (gather src)
__device__ __half g_xh[(size_t)NN * HD];    // activation fp16 (GEMM in)
__device__ int    g_deg_out[NN];
__device__ int    g_deg_in[NN];
__device__ float  g_norm_out[NN];
__device__ float  g_norm_in[NN];
__device__ int    g_offs[NN + 1];
__device__ int    g_cursor[NN];
__device__ int    g_bsums[128];
__device__ int    g_csr[EE];

// Pre-built W operand tiles: [n][k] fp16, padded row stride 136 elems.
__device__ __align__(16) unsigned char g_B0h[128 * 136 * 2];
__device__ __align__(16) unsigned char g_B1h[128 * 136 * 2];
__device__ __align__(16) unsigned char g_B2h[64 * 136 * 2];

// ===========================================================================
// helpers (baseline sm_80 features -- no 'a'-gated PTX)
// ===========================================================================
__device__ __forceinline__ uint32_t smem_to_u32(const void* p) {
    uint32_t a;
    asm("{ .reg .u64 t; cvta.to.shared.u64 t, %1; cvt.u32.u64 %0, t; }"
        : "=r"(a) : "l"(p));
    return a;
}

#define LDSM4(r, addr) \
    asm volatile("ldmatrix.sync.aligned.m8n8.x4.shared.b16 {%0,%1,%2,%3}, [%4];" \
        : "=r"((r)[0]), "=r"((r)[1]), "=r"((r)[2]), "=r"((r)[3]) : "r"(addr))

#define MMA_F16(d, a, b0, b1) \
    asm volatile("mma.sync.aligned.m16n8k16.row.col.f32.f16.f16.f32 " \
        "{%0,%1,%2,%3}, {%4,%5,%6,%7}, {%8,%9}, {%0,%1,%2,%3};" \
        : "+f"((d)[0]), "+f"((d)[1]), "+f"((d)[2]), "+f"((d)[3]) \
        : "r"((a)[0]), "r"((a)[1]), "r"((a)[2]), "r"((a)[3]), "r"(b0), "r"(b1))

#define CP_ASYNC16(dst_u32, src_ptr) \
    asm volatile("cp.async.cg.shared.global [%0], [%1], 16;" \
        :: "r"(dst_u32), "l"(src_ptr) : "memory")
#define CP_COMMIT() asm volatile("cp.async.commit_group;" ::: "memory")
#define CP_WAIT0()  asm volatile("cp.async.wait_group 0;" ::: "memory")

// ===========================================================================
// Degrees + norms + CSR build
// ===========================================================================
__global__ void k_zero() {
    int i = blockIdx.x * blockDim.x + threadIdx.x;
    if (i < NN) { g_deg_out[i] = 0; g_deg_in[i] = 0; g_cursor[i] = 0; }
}

__global__ void k_deg(const int* __restrict__ src, const int* __restrict__ dst) {
    int e = blockIdx.x * blockDim.x + threadIdx.x;
    if (e < EE) {
        atomicAdd(&g_deg_out[src[e]], 1);
        atomicAdd(&g_deg_in[dst[e]], 1);
    }
}

// Fused: per-node norms + W-tile build ([n][k] fp16, stride 136)
__global__ void k_norm_wtiles(const float* __restrict__ W0,
                              const float* __restrict__ W1,
                              const float* __restrict__ W2) {
    int i = blockIdx.x * blockDim.x + threadIdx.x;
    if (i < NN) {
        int d0 = g_deg_out[i];
        int d1 = g_deg_in[i];
        g_norm_out[i] = d0 > 0 ? rsqrtf((float)d0) : 0.f;
        g_norm_in[i]  = d1 > 0 ? rsqrtf((float)d1) : 0.f;
    }
    if (i < 40960) {
        float val;
        unsigned char *ph;
        int n, k;
        if (i < 32768) {
            const float* W = (i < 16384) ? W0 : W1;
            ph = (i < 16384) ? g_B0h : g_B1h;
            int e = i & 16383;
            n = e >> 7; k = e & 127;
            val = W[k * 128 + n];
        } else {
            int e = i - 32768;
            n = e >> 7; k = e & 127;      // n in [0,64)
            val = (n < CD) ? W2[k * CD + n] : 0.f;
            ph = g_B2h;
        }
        uint32_t off = ((uint32_t)n * 136u + (uint32_t)k) * 2u;
        *(__half*)(ph + off) = __float2half_rn(val);
    }
}

// Convert input features fp32 -> fp16 buffer (one float4 per thread)
__global__ void k_feat(const float* __restrict__ feat) {
    size_t i = (size_t)blockIdx.x * blockDim.x + threadIdx.x;
    if (i >= (size_t)NN * 32) return;
    float4 v = ((const float4*)feat)[i];
    __half2 hp0 = __floats2half2_rn(v.x, v.y);
    __half2 hp1 = __floats2half2_rn(v.z, v.w);
    uint2 hv = make_uint2(*(uint32_t*)&hp0, *(uint32_t*)&hp1);
    ((uint2*)g_xh)[i] = hv;
}

__global__ void k_scan1() {
    __shared__ int sh[1024];
    int i = blockIdx.x * 1024 + threadIdx.x;
    int v = (i < NN) ? g_deg_in[i] : 0;
    sh[threadIdx.x] = v;
    __syncthreads();
    #pragma unroll
    for (int d = 1; d < 1024; d <<= 1) {
        int t = 0;
        if ((int)threadIdx.x >= d) t = sh[threadIdx.x - d];
        __syncthreads();
        sh[threadIdx.x] += t;
        __syncthreads();
    }
    if (i < NN) g_offs[i + 1] = sh[threadIdx.x];
    if (threadIdx.x == 1023) g_bsums[blockIdx.x] = sh[1023];
}

__global__ void k_scan2(int nb) {
    __shared__ int sh[128];
    int t = threadIdx.x;
    int v = (t < nb) ? g_bsums[t] : 0;
    sh[t] = v;
    __syncthreads();
    #pragma unroll
    for (int d = 1; d < 128; d <<= 1) {
        int x = 0;
        if (t >= d) x = sh[t - d];
        __syncthreads();
        sh[t] += x;
        __syncthreads();
    }
    if (t < nb) g_bsums[t] = sh[t] - v;   // exclusive
}

__global__ void k_scan3() {
    int i = blockIdx.x * blockDim.x + threadIdx.x;
    if (i == 0) g_offs[0] = 0;
    if (i < NN) g_offs[i + 1] += g_bsums[i >> 10];
}

__global__ void k_scatter(const int* __restrict__ src, const int* __restrict__ dst) {
    int e = blockIdx.x * blockDim.x + threadIdx.x;
    if (e < EE) {
        int d = dst[e];
        int pos = g_offs[d] + atomicAdd(&g_cursor[d], 1);
        g_csr[pos] = src[e];
    }
}

// ===========================================================================
// Persistent HMMA GEMM: hout[r,0:OUTC] = fp16(norm_out[r] * (x[r,:] @ W))
// SINGLE-TERM fp16: D = A*B (A fp16, W fp16, fp32 accumulate).
// X fp16 in global -> cp.async into double-buffered smem.
// 512 thr, one barrier per tile.
// ===========================================================================
template <int NTILE, int OUTC>
__global__ void __launch_bounds__(512)
gemm_pers(const __half* __restrict__ xh,
          const unsigned char* __restrict__ Wh,
          __half* __restrict__ hout) {
    extern __shared__ __align__(16) unsigned char sm[];
    constexpr int XS     = 136;                    // fp16 row stride (elems)
    constexpr int XBUF   = 128 * XS * 2;           // 34816 (one stage)
    constexpr int W_OFF  = 2 * XBUF;               // 69632
    constexpr int WBYTES = NTILE * XS * 2;
    constexpr int NWTILE = NTILE / 4;              // warp n-tile (32 or 16)
    constexpr int NFRAG  = NWTILE / 8;             // n8 frags (4 or 2)
    constexpr int NF2    = NFRAG / 2;              // LDSM.x4 count (2 or 1)

    const int tid  = threadIdx.x;
    const int wid  = tid >> 5;
    const int lane = tid & 31;

    const uint32_t smb = smem_to_u32(sm);

    // prefetch lane mapping: 4 threads/row; each does 64B (4 x 16B)
    const int pr = tid >> 2;               // row 0..127
    const int ph = tid & 3;                // 32-elem quarter
    const uint32_t prel = (uint32_t)((pr * XS + ph * 32) * 2);  // byte off in buf

    auto prefetch = [&](int t, int buf) {
        const uint32_t base = smb + buf * XBUF;
        int gr = t * 128 + pr;
        if (gr < NN) {
            const __half* sh_ = &xh[(size_t)gr * 128 + ph * 32];
            #pragma unroll
            for (int i = 0; i < 4; i++)
                CP_ASYNC16(base + prel + i * 16, sh_ + i * 8);
        } else {
            uint4 z = make_uint4(0, 0, 0, 0);
            #pragma unroll
            for (int i = 0; i < 4; i++)
                *(uint4*)(sm + buf * XBUF + prel + i * 16) = z;
        }
    };

    prefetch(blockIdx.x, 0);
    CP_COMMIT();

    // ---- W: copy once ----
    {
        const float4* s4h = (const float4*)Wh;
        float4* d4h = (float4*)(sm + W_OFF);
        for (int i = tid; i < WBYTES / 16; i += 512) d4h[i] = s4h[i];
    }

    const int m0 = (wid & 3) * 32;
    const int n0 = (wid >> 2) * NWTILE;
    const uint32_t aRel =
        (uint32_t)(((m0 + (lane & 15)) * XS + (lane >> 4) * 8) * 2);
    const uint32_t bH0 = smb + W_OFF +
        (uint32_t)(((n0 + (lane >> 4) * 8 + (lane & 7)) * XS + ((lane >> 3) & 1) * 8) * 2);

    const int g  = lane >> 2;
    const int tq = lane & 3;

    int buf = 0;
    for (int t = blockIdx.x; t < NTILES; t += gridDim.x, buf ^= 1) {
        const int row0 = t * 128;

        CP_WAIT0();
        __syncthreads();    // buf ready; all warps done reading prev buf

        // ---- prefetch next tile into the other buffer (overlaps mainloop) ----
        {
            int tn = t + gridDim.x;
            if (tn < NTILES) prefetch(tn, buf ^ 1);
            CP_COMMIT();
        }

        // ---- mainloop: 8 k-steps, fragment double-buffer ----
        float acc[2][NFRAG][4];
        #pragma unroll
        for (int mi = 0; mi < 2; mi++)
            #pragma unroll
            for (int f = 0; f < NFRAG; f++)
                #pragma unroll
                for (int q = 0; q < 4; q++) acc[mi][f][q] = 0.f;

        uint32_t AHf[2][2][4];
        uint32_t BHf[2][NF2][4];

        uint32_t aH = smb + buf * XBUF + aRel;
        uint32_t bH = bH0;
        LDSM4(AHf[0][0], aH);
        LDSM4(AHf[0][1], aH + 16 * XS * 2);
        #pragma unroll
        for (int j = 0; j < NF2; j++)
            LDSM4(BHf[0][j], bH + j * 16 * XS * 2);

        #pragma unroll
        for (int ks = 0; ks < 8; ks++) {
            const int cur = ks & 1;
            const int nxt = cur ^ 1;
            if (ks < 7) {
                aH += 32; bH += 32;
                LDSM4(AHf[nxt][0], aH);
                LDSM4(AHf[nxt][1], aH + 16 * XS * 2);
                #pragma unroll
                for (int j = 0; j < NF2; j++)
                    LDSM4(BHf[nxt][j], bH + j * 16 * XS * 2);
            }
            #pragma unroll
            for (int mi = 0; mi < 2; mi++)
                #pragma unroll
                for (int j = 0; j < NF2; j++)
                    #pragma unroll
                    for (int h = 0; h < 2; h++)
                        MMA_F16(acc[mi][j * 2 + h], AHf[cur][mi],
                                BHf[cur][j][h * 2], BHf[cur][j][h * 2 + 1]);
        }

        // ---- epilogue: scale by norm_out, store fp16 ----
        #pragma unroll
        for (int mi = 0; mi < 2; mi++) {
            int r1 = row0 + m0 + mi * 16 + g;
            int r2 = r1 + 8;
            float s1 = (r1 < NN) ? g_norm_out[r1] : 0.f;
            float s2 = (r2 < NN) ? g_norm_out[r2] : 0.f;
            #pragma unroll
            for (int f = 0; f < NFRAG; f++) {
                int n = n0 + f * 8 + tq * 2;
                if (OUTC < NTILE && n >= OUTC) continue;
                float* c = acc[mi][f];
                if (r1 < NN) {
                    __half2 hv = __floats2half2_rn(c[0] * s1, c[1] * s1);
                    *(__half2*)&hout[(size_t)r1 * OUTC + n] = hv;
                }
                if (r2 < NN) {
                    __half2 hv = __floats2half2_rn(c[2] * s2, c[3] * s2);
                    *(__half2*)&hout[(size_t)r2 * OUTC + n] = hv;
                }
            }
        }
    }
}

// ===========================================================================
// Aggregation 128-dim: one warp per dst node; CSR gather (fp16), fp32 accum.
// Writes fp16 activation buffer (GEMM input format).
// ===========================================================================
__global__ void __launch_bounds__(256)
agg128(const float* __restrict__ bias) {
    int w = (blockIdx.x * blockDim.x + threadIdx.x) >> 5;
    if (w >= NN) return;
    int lane = threadIdx.x & 31;
    int beg = g_offs[w], end = g_offs[w + 1];

    float4 acc = make_float4(0.f, 0.f, 0.f, 0.f);
    int e = beg;
    for (; e + 4 <= end; e += 4) {
        int s0 = g_csr[e],     s1 = g_csr[e + 1];
        int s2 = g_csr[e + 2], s3 = g_csr[e + 3];
        uint2 u0 = *(const uint2*)&g_hbuf[(size_t)s0 * 128 + lane * 4];
        uint2 u1 = *(const uint2*)&g_hbuf[(size_t)s1 * 128 + lane * 4];
        uint2 u2 = *(const uint2*)&g_hbuf[(size_t)s2 * 128 + lane * 4];
        uint2 u3 = *(const uint2*)&g_hbuf[(size_t)s3 * 128 + lane * 4];
        float2 a0 = __half22float2(*(__half2*)&u0.x), b0 = __half22float2(*(__half2*)&u0.y);
        float2 a1 = __half22float2(*(__half2*)&u1.x), b1 = __half22float2(*(__half2*)&u1.y);
        float2 a2 = __half22float2(*(__half2*)&u2.x), b2 = __half22float2(*(__half2*)&u2.y);
        float2 a3 = __half22float2(*(__half2*)&u3.x), b3 = __half22float2(*(__half2*)&u3.y);
        acc.x += (a0.x + a1.x) + (a2.x + a3.x);
        acc.y += (a0.y + a1.y) + (a2.y + a3.y);
        acc.z += (b0.x + b1.x) + (b2.x + b3.x);
        acc.w += (b0.y + b1.y) + (b2.y + b3.y);
    }
    for (; e < end; e++) {
        int s0 = g_csr[e];
        uint2 u0 = *(const uint2*)&g_hbuf[(size_t)s0 * 128 + lane * 4];
        float2 a0 = __half22float2(*(__half2*)&u0.x), b0 = __half22float2(*(__half2*)&u0.y);
        acc.x += a0.x; acc.y += a0.y; acc.z += b0.x; acc.w += b0.y;
    }

    float sc = g_norm_in[w];
    float4 b = *(const float4*)&bias[lane * 4];
    float4 o;
    o.x = fmaxf(fmaf(acc.x, sc, b.x), 0.f);
    o.y = fmaxf(fmaf(acc.y, sc, b.y), 0.f);
    o.z = fmaxf(fmaf(acc.z, sc, b.z), 0.f);
    o.w = fmaxf(fmaf(acc.w, sc, b.w), 0.f);

    __half2 hp0 = __floats2half2_rn(o.x, o.y);
    __half2 hp1 = __floats2half2_rn(o.z, o.w);
    uint2 hv = make_uint2(*(uint32_t*)&hp0, *(uint32_t*)&hp1);
    *(uint2*)&g_xh[(size_t)w * 128 + lane * 4] = hv;
}

// ===========================================================================
// Aggregation 40-dim (final layer, no relu) -> d_out (fp32)
// ===========================================================================
__global__ void __launch_bounds__(256)
agg40(const float* __restrict__ bias, float* __restrict__ out) {
    int w = (blockIdx.x * blockDim.x + threadIdx.x) >> 5;
    if (w >= NN) return;
    int lane = threadIdx.x & 31;
    int beg = g_offs[w], end = g_offs[w + 1];
    if (lane >= 20) return;

    float2 acc = make_float2(0.f, 0.f);
    int e = beg;
    for (; e + 2 <= end; e += 2) {
        int s0 = g_csr[e], s1 = g_csr[e + 1];
        __half2 h0 = *(const __half2*)&g_hbuf[(size_t)s0 * 40 + lane * 2];
        __half2 h1 = *(const __half2*)&g_hbuf[(size_t)s1 * 40 + lane * 2];
        float2 f0 = __half22float2(h0);
        float2 f1 = __half22float2(h1);
        acc.x += f0.x + f1.x;
        acc.y += f0.y + f1.y;
    }
    if (e < end) {
        int s0 = g_csr[e];
        float2 f0 = __half22float2(*(const __half2*)&g_hbuf[(size_t)s0 * 40 + lane * 2]);
        acc.x += f0.x; acc.y += f0.y;
    }
    float sc = g_norm_in[w];
    float2 o;
    o.x = fmaf(acc.x, sc, bias[lane * 2]);
    o.y = fmaf(acc.y, sc, bias[lane * 2 + 1]);
    *(float2*)&out[(size_t)w * 40 + lane * 2] = o;
}

// ===========================================================================
extern "C" void kernel_launch(void* const* d_in, const int* in_sizes, int n_in,
                              void* d_out, int out_size) {
    const float* feat = (const float*)d_in[0];
    const int*   src  = (const int*)  d_in[1];
    const int*   dst  = (const int*)  d_in[2];
    const float* W0   = (const float*)d_in[3];
    const float* b0   = (const float*)d_in[4];
    const float* W1   = (const float*)d_in[5];
    const float* b1   = (const float*)d_in[6];
    const float* W2   = (const float*)d_in[7];
    const float* b2   = (const float*)d_in[8];
    float* out = (float*)d_out;

    const int NB = (NN + 255) / 256;
    const int EB = (EE + 255) / 256;
    const int SB = (NN + 1023) / 1024;
    const int AGGB = (NN * 32 + 255) / 256;
    const int FB = (NN * 32 + 255) / 256;

    // smem: X double-buffer 2*34816 = 69632 ; W = NTILE*136*2
    const int SMEM_BIG   = 2 * 128 * 136 * 2 + 128 * 136 * 2;  // 104448
    const int SMEM_SMALL = 2 * 128 * 136 * 2 + 64 * 136 * 2;   // 87040

    static cudaStream_t s2 = nullptr;
    static cudaEvent_t evF = nullptr, evJ = nullptr;
    static bool init_done = false;
    if (!init_done) {
        cudaFuncSetAttribute(gemm_pers<128, 128>,
                             cudaFuncAttributeMaxDynamicSharedMemorySize, SMEM_BIG);
        cudaFuncSetAttribute(gemm_pers<64, 40>,
                             cudaFuncAttributeMaxDynamicSharedMemorySize, SMEM_SMALL);
        cudaStreamCreateWithFlags(&s2, cudaStreamNonBlocking);
        cudaEventCreateWithFlags(&evF, cudaEventDisableTiming);
        cudaEventCreateWithFlags(&evJ, cudaEventDisableTiming);
        init_done = true;
    }

    unsigned char *p_B0h, *p_B1h, *p_B2h;
    cudaGetSymbolAddress((void**)&p_B0h, g_B0h);
    cudaGetSymbolAddress((void**)&p_B1h, g_B1h);
    cudaGetSymbolAddress((void**)&p_B2h, g_B2h);
    __half* p_hbuf;
    __half* p_xh;
    cudaGetSymbolAddress((void**)&p_hbuf, g_hbuf);
    cudaGetSymbolAddress((void**)&p_xh, g_xh);

    // common prep
    k_zero<<<NB, 256>>>();
    k_deg<<<EB, 256>>>(src, dst);
    k_norm_wtiles<<<NB, 256>>>(W0, W1, W2);

    // fork: feat-convert + layer-0 GEMM on s2, CSR build on main stream
    cudaEventRecord(evF, 0);
    cudaStreamWaitEvent(s2, evF, 0);
    k_feat<<<FB, 256, 0, s2>>>(feat);
    gemm_pers<128, 128><<<PGRID, 512, SMEM_BIG, s2>>>(p_xh, p_B0h, p_hbuf);
    k_scan1<<<SB, 1024>>>();
    k_scan2<<<1, 128>>>(SB);
    k_scan3<<<NB, 256>>>();
    k_scatter<<<EB, 256>>>(src, dst);
    cudaEventRecord(evJ, s2);
    cudaStreamWaitEvent(0, evJ, 0);

    // layer 0 aggregation (writes g_xh for next GEMM)
    agg128<<<AGGB, 256>>>(b0);
    // layer 1
    gemm_pers<128, 128><<<PGRID, 512, SMEM_BIG>>>(p_xh, p_B1h, p_hbuf);
    agg128<<<AGGB, 256>>>(b1);
    // layer 2
    gemm_pers<64, 40><<<PGRID, 512, SMEM_SMALL>>>(p_xh, p_B2h, p_hbuf);
    agg40<<<AGGB, 256>>>(b2, out);
}